// round 5
// baseline (speedup 1.0000x reference)
#include <cuda_runtime.h>
#include <cuda_fp16.h>
#include <cstdint>
#include <cstddef>

#define HH 1024
#define TT 256
#define BB 64
#define BT (BB*TT)       /* 16384 */
#define G4 (4*HH)        /* 4096 */
#define NBLK_REC 128

/* fp16 GEMM tile constants (stride in halves) */
#define HSTR 40
#define L_ST (256*HSTR)             /* lstm1 stage halves (A128+B128) */
#define G_AT (128*HSTR)             /* gemm A region halves */
#define G_STG (384*HSTR)            /* gemm stage halves (A128+B256)  */

/* recurrence smem byte offsets */
#define R_WS_B   0
#define R_TB_B   66048              /* Ws: 32*1032 halves = 66048 B  */
#define R_PART_B 131584             /* tbuf: 2*16384 halves = 65536  */
#define R_MBAR_B 201216             /* part: 8*2176 f32 = 69632      */
#define R_SMEM_B 201232
#define RP_STR 34
#define RP_SZ  (64*RP_STR)

/* fp16 scratch offsets (halves) */
#define X16_OFF  0u
#define W_L1A    4194304u
#define W_L1B    5242880u
#define W_L2A    9437184u
#define W_L2B    13631488u
#define W_M1     17825792u
#define W_M2     18874368u
#define W16_TOT  19398656u

// ------------------------- scratch (device globals) --------------------------
__device__ __align__(256) float  g_gates[(size_t)BT * G4];   // fp32 xg scratch
__device__ __align__(256) __half g_w16[W16_TOT];             // converted x + weights
__device__ __align__(256) __half g_h1[(size_t)BT * HH];
__device__ __align__(256) __half g_h2[(size_t)BT * HH];
__device__ __align__(256) __half g_hT[2 * HH * BB];          // transposed swizzled h
__device__ __align__(256) __half g_z1[BB * HH];
__device__ __align__(256) __half g_z2[BB * (HH/2)];
__device__ volatile unsigned g_cnt = 0;
__device__ volatile unsigned g_sense = 0;

// ------------------------- helpers ------------------------------------------
__device__ __forceinline__ uint32_t ld_u32h(const __half* p) {
    return *(const uint32_t*)p;
}
__device__ __forceinline__ void mma_fp16(float c[4],
                                         uint32_t a0, uint32_t a1, uint32_t a2, uint32_t a3,
                                         uint32_t b0, uint32_t b1) {
    asm volatile(
        "mma.sync.aligned.m16n8k16.row.col.f32.f16.f16.f32 "
        "{%0,%1,%2,%3}, {%4,%5,%6,%7}, {%8,%9}, {%0,%1,%2,%3};"
        : "+f"(c[0]), "+f"(c[1]), "+f"(c[2]), "+f"(c[3])
        : "r"(a0), "r"(a1), "r"(a2), "r"(a3), "r"(b0), "r"(b1));
}
__device__ __forceinline__ float sigf(float x) { return 1.0f / (1.0f + expf(-x)); }

__device__ __forceinline__ void cp16(uint32_t dsh, const void* src) {
    asm volatile("cp.async.cg.shared.global [%0], [%1], 16;" :: "r"(dsh), "l"(src));
}
__device__ __forceinline__ void cp_commit() { asm volatile("cp.async.commit_group;"); }

__device__ __forceinline__ void mbar_init(uint32_t mbar, uint32_t cnt) {
    asm volatile("mbarrier.init.shared.b64 [%0], %1;" :: "r"(mbar), "r"(cnt) : "memory");
}
__device__ __forceinline__ void mbar_expect(uint32_t mbar, uint32_t bytes) {
    asm volatile("mbarrier.arrive.expect_tx.shared.b64 _, [%0], %1;" :: "r"(mbar), "r"(bytes) : "memory");
}
__device__ __forceinline__ void bulk_g2s(uint32_t dst, const void* src, uint32_t bytes, uint32_t mbar) {
    asm volatile("cp.async.bulk.shared::cluster.global.mbarrier::complete_tx::bytes [%0], [%1], %2, [%3];"
                 :: "r"(dst), "l"(src), "r"(bytes), "r"(mbar) : "memory");
}
__device__ __forceinline__ void mbar_wait(uint32_t mbar, uint32_t parity) {
    uint32_t done;
    asm volatile(
        "{\n\t.reg .pred p;\n\t"
        "mbarrier.try_wait.parity.acquire.cta.shared::cta.b64 p, [%1], %2;\n\t"
        "selp.b32 %0, 1, 0, p;\n\t}"
        : "=r"(done) : "r"(mbar), "r"(parity) : "memory");
    if (!done) {
        asm volatile(
            "{\n\t.reg .pred P1;\n\t"
            "WL_%=:\n\t"
            "mbarrier.try_wait.parity.acquire.cta.shared::cta.b64 P1, [%0], %1, 0x989680;\n\t"
            "@P1 bra.uni WD_%=;\n\t"
            "bra.uni WL_%=;\n\t"
            "WD_%=:\n\t}"
            :: "r"(mbar), "r"(parity) : "memory");
    }
}

// =============================================================================
// fp32 -> fp16 conversion of xx + 6 weight matrices (one launch)
// =============================================================================
__global__ void convert_kernel(const float* __restrict__ xx,
                               const float* __restrict__ w0, const float* __restrict__ w1,
                               const float* __restrict__ w2, const float* __restrict__ w3,
                               const float* __restrict__ w4, const float* __restrict__ w5)
{
    const uint32_t i4 = blockIdx.x * blockDim.x + threadIdx.x;   // float4 index
    const float* src; uint32_t base4;
    if      (i4 < 1048576u) { src = xx; base4 = 0u; }
    else if (i4 < 1310720u) { src = w0; base4 = 1048576u; }
    else if (i4 < 2359296u) { src = w1; base4 = 1310720u; }
    else if (i4 < 3407872u) { src = w2; base4 = 2359296u; }
    else if (i4 < 4456448u) { src = w3; base4 = 3407872u; }
    else if (i4 < 4718592u) { src = w4; base4 = 4456448u; }
    else                    { src = w5; base4 = 4718592u; }
    const float4 v = ((const float4*)src)[i4 - base4];
    __half2* dst = (__half2*)(g_w16 + (size_t)i4 * 4);
    dst[0] = __floats2half2_rn(v.x, v.y);
    dst[1] = __floats2half2_rn(v.z, v.w);
}

// =============================================================================
// fp16 GEMM: C = A @ W^T (+bias, +ReLU). BM=128, BN=256, BK=32, 3-stage.
// 8 warps 2(M)x4(N), warp tile 64x64, m16n8k16.
// =============================================================================
template<int RELU, int HOUT>
__launch_bounds__(256, 1)
__global__ void gemm16_kernel(const __half* __restrict__ A, long long asr,
                              const __half* __restrict__ W,
                              const float* __restrict__ b1p, const float* __restrict__ b2p,
                              void* __restrict__ Cv, int M, int N, int K)
{
    extern __shared__ __half smh[];
    const int tid = threadIdx.x, lane = tid & 31, warp = tid >> 5;
    const int wm = warp >> 2, wn = warp & 3;
    const int g = lane >> 2, q = lane & 3;
    const int mb = blockIdx.y * 128, nb = blockIdx.x * 256;

    float acc[4][8][4];
#pragma unroll
    for (int a = 0; a < 4; a++)
#pragma unroll
        for (int b = 0; b < 8; b++)
#pragma unroll
            for (int c = 0; c < 4; c++) acc[a][b][c] = 0.0f;

    const uint32_t smb = (uint32_t)__cvta_generic_to_shared(smh);
    const __half* aptr[2]; uint32_t adst[2];
#pragma unroll
    for (int i = 0; i < 2; i++) {
        const int slot = tid + i * 256;
        const int row = slot >> 2, kc = (slot & 3) * 8;
        int gr = mb + row; if (gr > M - 1) gr = M - 1;
        aptr[i] = A + (size_t)gr * asr + kc;
        adst[i] = smb + (uint32_t)((row * HSTR + kc) * 2);
    }
    const __half* bptr[4]; uint32_t bdst[4];
#pragma unroll
    for (int i = 0; i < 4; i++) {
        const int slot = tid + i * 256;
        const int row = slot >> 2, kc = (slot & 3) * 8;
        bptr[i] = W + (size_t)(nb + row) * K + kc;
        bdst[i] = smb + (uint32_t)((G_AT + row * HSTR + kc) * 2);
    }

    const int KT = K >> 5;
    auto issue = [&](int kt) {
        const uint32_t so = (uint32_t)((kt % 3) * G_STG * 2);
        const int koff = kt * 32;
#pragma unroll
        for (int i = 0; i < 2; i++) cp16(adst[i] + so, aptr[i] + koff);
#pragma unroll
        for (int i = 0; i < 4; i++) cp16(bdst[i] + so, bptr[i] + koff);
        cp_commit();
    };

    issue(0); if (KT > 1) issue(1);

    for (int kt = 0; kt < KT; ++kt) {
        if (kt < KT - 1) asm volatile("cp.async.wait_group 1;");
        else             asm volatile("cp.async.wait_group 0;");
        __syncthreads();
        if (kt + 2 < KT) issue(kt + 2);

        const __half* Ab = smh + (kt % 3) * G_STG;
        const __half* Bb = Ab + G_AT;
#pragma unroll
        for (int kk = 0; kk < 32; kk += 16) {
            uint32_t af[4][4], bfr[8][2];
#pragma unroll
            for (int mt = 0; mt < 4; mt++) {
                const int r = wm * 64 + mt * 16 + g;
                af[mt][0] = ld_u32h(Ab + r * HSTR + kk + 2 * q);
                af[mt][1] = ld_u32h(Ab + (r + 8) * HSTR + kk + 2 * q);
                af[mt][2] = ld_u32h(Ab + r * HSTR + kk + 2 * q + 8);
                af[mt][3] = ld_u32h(Ab + (r + 8) * HSTR + kk + 2 * q + 8);
            }
#pragma unroll
            for (int nt = 0; nt < 8; nt++) {
                const int n = wn * 64 + nt * 8 + g;
                bfr[nt][0] = ld_u32h(Bb + n * HSTR + kk + 2 * q);
                bfr[nt][1] = ld_u32h(Bb + n * HSTR + kk + 2 * q + 8);
            }
#pragma unroll
            for (int mt = 0; mt < 4; mt++)
#pragma unroll
                for (int nt = 0; nt < 8; nt++)
                    mma_fp16(acc[mt][nt], af[mt][0], af[mt][1], af[mt][2], af[mt][3],
                             bfr[nt][0], bfr[nt][1]);
        }
    }

#pragma unroll
    for (int mt = 0; mt < 4; mt++) {
#pragma unroll
        for (int nt = 0; nt < 8; nt++) {
            const int row0 = mb + wm * 64 + mt * 16 + g;
            const int col  = nb + wn * 64 + nt * 8 + 2 * q;
            const float b0v = (b1p ? b1p[col]     : 0.f) + (b2p ? b2p[col]     : 0.f);
            const float b1v = (b1p ? b1p[col + 1] : 0.f) + (b2p ? b2p[col + 1] : 0.f);
            float v0 = acc[mt][nt][0] + b0v, v1 = acc[mt][nt][1] + b1v;
            float v2 = acc[mt][nt][2] + b0v, v3 = acc[mt][nt][3] + b1v;
            if (RELU) {
                v0 = fmaxf(v0, 0.f); v1 = fmaxf(v1, 0.f);
                v2 = fmaxf(v2, 0.f); v3 = fmaxf(v3, 0.f);
            }
            if (HOUT) {
                __half* C = (__half*)Cv;
                if (row0 < M)     *(__half2*)(C + (size_t)row0 * N + col)       = __floats2half2_rn(v0, v1);
                if (row0 + 8 < M) *(__half2*)(C + (size_t)(row0 + 8) * N + col) = __floats2half2_rn(v2, v3);
            } else {
                float* C = (float*)Cv;
                if (row0 < M)     *(float2*)(C + (size_t)row0 * N + col)       = make_float2(v0, v1);
                if (row0 + 8 < M) *(float2*)(C + (size_t)(row0 + 8) * N + col) = make_float2(v2, v3);
            }
        }
    }
}

// =============================================================================
// fused lstm1 (fp16): h = sig(o)*tanh(sig(i)*tanh(g)); f gate skipped.
// BM=128, BN=128, BK=32, 4-stage; 3 sequential gate phases.
// =============================================================================
__launch_bounds__(256, 1)
__global__ void lstm1_16_kernel(const __half* __restrict__ A, long long asr,
                                const __half* __restrict__ W,
                                const float* __restrict__ bih, const float* __restrict__ bhh,
                                __half* __restrict__ Hout, int M, int K)
{
    extern __shared__ __half smh[];
    const int tid = threadIdx.x, lane = tid & 31, warp = tid >> 5;
    const int wm = warp >> 2, wn = warp & 3;
    const int g = lane >> 2, q = lane & 3;
    const int mb = blockIdx.y * 128, nb = blockIdx.x * 128;

    const uint32_t smb = (uint32_t)__cvta_generic_to_shared(smh);
    const int rowS = tid >> 1, kcS = (tid & 1) * 8;  // 2 A slots + 2 B slots per thread? no:
    // A: 512 cp16 ops -> 2/thread via slots tid, tid+256 (row=slot>>2, kc=(slot&3)*8)
    (void)rowS; (void)kcS;

    int arow[2]; const __half* aptr[2]; uint32_t adst[2];
#pragma unroll
    for (int i = 0; i < 2; i++) {
        const int slot = tid + i * 256;
        const int row = slot >> 2, kc = (slot & 3) * 8;
        int gr = mb + row; if (gr > M - 1) gr = M - 1;
        arow[i] = row;
        aptr[i] = A + (size_t)gr * asr + kc;
        adst[i] = smb + (uint32_t)((row * HSTR + kc) * 2);
    }
    uint32_t bdst[2]; int brow[2], bkc[2];
#pragma unroll
    for (int i = 0; i < 2; i++) {
        const int slot = tid + i * 256;
        brow[i] = slot >> 2; bkc[i] = (slot & 3) * 8;
        bdst[i] = smb + (uint32_t)(((128 + brow[i]) * HSTR + bkc[i]) * 2);
    }

    const int KT = K >> 5;
    float keep[4][4][4];
    const int gset[3] = {0, 2, 3};

#pragma unroll 1
    for (int ph = 0; ph < 3; ++ph) {
        const int gate = gset[ph];
        const __half* Wb = W + ((size_t)(gate * HH + nb)) * K;

        float acc[4][4][4];
#pragma unroll
        for (int a = 0; a < 4; a++)
#pragma unroll
            for (int b = 0; b < 4; b++)
#pragma unroll
                for (int c = 0; c < 4; c++) acc[a][b][c] = 0.0f;

        auto issue = [&](int kt) {
            const int koff = kt * 32;
            const uint32_t so = (uint32_t)((kt & 3) * L_ST * 2);
#pragma unroll
            for (int i = 0; i < 2; i++) cp16(adst[i] + so, aptr[i] + koff);
#pragma unroll
            for (int i = 0; i < 2; i++) cp16(bdst[i] + so, Wb + (size_t)brow[i] * K + bkc[i] + koff);
            cp_commit();
        };

        const int pre = KT < 3 ? KT : 3;
        for (int s = 0; s < pre; ++s) issue(s);

        for (int kt = 0; kt < KT; ++kt) {
            if (kt < KT - 2)       asm volatile("cp.async.wait_group 2;");
            else if (kt == KT - 2) asm volatile("cp.async.wait_group 1;");
            else                   asm volatile("cp.async.wait_group 0;");
            __syncthreads();
            if (kt + 3 < KT) issue(kt + 3);

            const __half* Ab = smh + (kt & 3) * L_ST;
            const __half* Bb = Ab + 128 * HSTR;
#pragma unroll
            for (int kk = 0; kk < 32; kk += 16) {
                uint32_t af[4][4], bfr[4][2];
#pragma unroll
                for (int mt = 0; mt < 4; mt++) {
                    const int r = wm * 64 + mt * 16 + g;
                    af[mt][0] = ld_u32h(Ab + r * HSTR + kk + 2 * q);
                    af[mt][1] = ld_u32h(Ab + (r + 8) * HSTR + kk + 2 * q);
                    af[mt][2] = ld_u32h(Ab + r * HSTR + kk + 2 * q + 8);
                    af[mt][3] = ld_u32h(Ab + (r + 8) * HSTR + kk + 2 * q + 8);
                }
#pragma unroll
                for (int nt = 0; nt < 4; nt++) {
                    const int n = wn * 32 + nt * 8 + g;
                    bfr[nt][0] = ld_u32h(Bb + n * HSTR + kk + 2 * q);
                    bfr[nt][1] = ld_u32h(Bb + n * HSTR + kk + 2 * q + 8);
                }
#pragma unroll
                for (int mt = 0; mt < 4; mt++)
#pragma unroll
                    for (int nt = 0; nt < 4; nt++)
                        mma_fp16(acc[mt][nt], af[mt][0], af[mt][1], af[mt][2], af[mt][3],
                                 bfr[nt][0], bfr[nt][1]);
            }
        }
        __syncthreads();

#pragma unroll
        for (int mt = 0; mt < 4; mt++) {
#pragma unroll
            for (int nt = 0; nt < 4; nt++) {
                const int gcol = gate * HH + nb + wn * 32 + nt * 8 + 2 * q;
                const float b0 = bih[gcol] + bhh[gcol];
                const float b1 = bih[gcol + 1] + bhh[gcol + 1];
                if (ph == 0) {
                    keep[mt][nt][0] = sigf(acc[mt][nt][0] + b0);
                    keep[mt][nt][1] = sigf(acc[mt][nt][1] + b1);
                    keep[mt][nt][2] = sigf(acc[mt][nt][2] + b0);
                    keep[mt][nt][3] = sigf(acc[mt][nt][3] + b1);
                } else if (ph == 1) {
                    keep[mt][nt][0] *= tanhf(acc[mt][nt][0] + b0);
                    keep[mt][nt][1] *= tanhf(acc[mt][nt][1] + b1);
                    keep[mt][nt][2] *= tanhf(acc[mt][nt][2] + b0);
                    keep[mt][nt][3] *= tanhf(acc[mt][nt][3] + b1);
                } else {
                    const int row0 = mb + wm * 64 + mt * 16 + g;
                    const int colh = nb + wn * 32 + nt * 8 + 2 * q;
                    const float v0 = sigf(acc[mt][nt][0] + b0) * tanhf(keep[mt][nt][0]);
                    const float v1 = sigf(acc[mt][nt][1] + b1) * tanhf(keep[mt][nt][1]);
                    const float v2 = sigf(acc[mt][nt][2] + b0) * tanhf(keep[mt][nt][2]);
                    const float v3 = sigf(acc[mt][nt][3] + b1) * tanhf(keep[mt][nt][3]);
                    if (row0 < M)     *(__half2*)(Hout + (size_t)row0 * HH + colh)       = __floats2half2_rn(v0, v1);
                    if (row0 + 8 < M) *(__half2*)(Hout + (size_t)(row0 + 8) * HH + colh) = __floats2half2_rn(v2, v3);
                }
            }
        }
    }
}

// ------------------------- grid barrier --------------------------------------
__device__ __forceinline__ void grid_bar()
{
    __threadfence();
    __syncthreads();
    if (threadIdx.x == 0) {
        const unsigned gen = g_sense;
        const unsigned arrived = atomicAdd((unsigned*)&g_cnt, 1u);
        if (arrived == NBLK_REC - 1u) {
            g_cnt = 0;
            __threadfence();
            atomicAdd((unsigned*)&g_sense, 1u);
        } else {
            while (g_sense == gen) { __nanosleep(32); }
        }
        __threadfence();
    }
    __syncthreads();
}

// =============================================================================
// RECURRENT LSTM LAYER (fp16 mma + TMA bulk chunks)
// 128 CTAs x 256 thr; CTA owns 8 h cols (32 gate rows). Whh slab fp16 in SMEM.
// h broadcast: 4 x 32KB fp16 chunks (pair-interleaved XOR-swizzled transposed
// layout), double-buffered TMA. 8-way K-split mma, fp32 partials in SMEM.
// =============================================================================
__launch_bounds__(256, 1)
__global__ void recur16_kernel(const float* __restrict__ xg,   // [BT, 4096] fp32
                               const float* __restrict__ Whh,  // [4096, 1024] fp32
                               __half* __restrict__ hs,        // [BT, 1024]
                               __half* __restrict__ hT,        // [2][65536] swizzled
                               int write_all)
{
    extern __shared__ char smc[];
    __half* Ws  = (__half*)(smc + R_WS_B);     // [32][1032]
    __half* tb  = (__half*)(smc + R_TB_B);     // 2 x 16384
    float* part = (float*)(smc + R_PART_B);    // 8 x [64][34]

    const uint32_t smb = (uint32_t)__cvta_generic_to_shared(smc);
    const uint32_t tb_sh = smb + R_TB_B;
    const uint32_t mb0 = smb + R_MBAR_B, mb1 = mb0 + 8;

    const int tid = threadIdx.x, lane = tid & 31;
    const int wk = tid >> 5;
    const int g = lane >> 2, q = lane & 3;
    const int n0 = blockIdx.x * 8;

    if (tid == 0) { mbar_init(mb0, 1); mbar_init(mb1, 1); }

    // Whh slab fp16: packed row c = gate*8 + j  <-  Whh[gate*HH + n0 + j]
#pragma unroll 1
    for (int c = 0; c < 32; c++) {
        const int gg = c >> 3, j = c & 7;
        const float4 v = *(const float4*)(Whh + ((size_t)(gg * HH + n0 + j)) * HH + tid * 4);
        __half* d = Ws + c * 1032 + tid * 4;
        d[0] = __float2half_rn(v.x); d[1] = __float2half_rn(v.y);
        d[2] = __float2half_rn(v.z); d[3] = __float2half_rn(v.w);
    }
    __syncthreads();

    // elementwise mapping
    const int er0 = tid >> 3, ej = tid & 7, er1 = er0 + 32;
    const int k_own = n0 + ej;
    const int c_own = k_own >> 8;
    const int t_own = (k_own & 255) >> 1;
    const int xr_own = 16 * (t_own & 3);
    const int pos_base = t_own * 128 + (k_own & 1);
    float cs0 = 0.f, cs1 = 0.f;

    for (int t = 0; t < TT; t++) {
        const __half* hsrc = hT + (size_t)(t & 1) * 65536;
        if (t > 0 && tid == 0) {
            mbar_expect(mb0, 32768);
            bulk_g2s(tb_sh, hsrc, 32768, mb0);
        }

        const size_t x0 = ((size_t)(er0 * TT + t)) * G4 + n0 + ej;
        const size_t x1 = ((size_t)(er1 * TT + t)) * G4 + n0 + ej;
        const float xi0 = xg[x0], xf0 = xg[x0 + 1024], xgg0 = xg[x0 + 2048], xo0 = xg[x0 + 3072];
        const float xi1 = xg[x1], xf1 = xg[x1 + 1024], xgg1 = xg[x1 + 2048], xo1 = xg[x1 + 3072];

        if (t > 0) {
            float acc[4][4][4];
#pragma unroll
            for (int a = 0; a < 4; a++)
#pragma unroll
                for (int b = 0; b < 4; b++)
#pragma unroll
                    for (int cc = 0; cc < 4; cc++) acc[a][b][cc] = 0.0f;

#pragma unroll 1
            for (int ch = 0; ch < 4; ++ch) {
                if (tid == 0 && ch < 3) {
                    const uint32_t m = ((ch + 1) & 1) ? mb1 : mb0;
                    mbar_expect(m, 32768);
                    bulk_g2s(tb_sh + ((ch + 1) & 1) * 32768u, hsrc + (ch + 1) * 16384, 32768, m);
                }
                mbar_wait((ch & 1) ? mb1 : mb0, (ch >> 1) & 1u);

                const __half* tA = tb + (ch & 1) * 16384;
#pragma unroll
                for (int kk = 0; kk < 2; ++kk) {
                    const int t_idx = wk * 16 + kk * 8 + q;
                    const int xr = 16 * (t_idx & 3);
                    const __half* p0 = tA + t_idx * 128;
                    const __half* p1 = tA + (t_idx + 4) * 128;
                    uint32_t a[4][4];
#pragma unroll
                    for (int mt = 0; mt < 4; mt++) {
                        const int r = mt * 16 + g;
                        a[mt][0] = ld_u32h(p0 + ((2 * r) ^ xr));
                        a[mt][1] = ld_u32h(p0 + ((2 * (r + 8)) ^ xr));
                        a[mt][2] = ld_u32h(p1 + ((2 * r) ^ xr));
                        a[mt][3] = ld_u32h(p1 + ((2 * (r + 8)) ^ xr));
                    }
                    const int kglob = ch * 256 + wk * 32 + kk * 16 + 2 * q;
                    uint32_t bfr[4][2];
#pragma unroll
                    for (int nt = 0; nt < 4; nt++) {
                        const int n = nt * 8 + g;
                        bfr[nt][0] = ld_u32h(Ws + n * 1032 + kglob);
                        bfr[nt][1] = ld_u32h(Ws + n * 1032 + kglob + 8);
                    }
#pragma unroll
                    for (int mt = 0; mt < 4; mt++)
#pragma unroll
                        for (int nt = 0; nt < 4; nt++)
                            mma_fp16(acc[mt][nt], a[mt][0], a[mt][1], a[mt][2], a[mt][3],
                                     bfr[nt][0], bfr[nt][1]);
                }
                __syncthreads();
            }

            // per-warp fp32 partials
            float* pw = part + wk * RP_SZ;
#pragma unroll
            for (int mt = 0; mt < 4; mt++) {
#pragma unroll
                for (int nt = 0; nt < 4; nt++) {
                    const int r = mt * 16 + g;
                    const int cc = nt * 8 + 2 * q;
                    *(float2*)(pw + r * RP_STR + cc)       = make_float2(acc[mt][nt][0], acc[mt][nt][1]);
                    *(float2*)(pw + (r + 8) * RP_STR + cc) = make_float2(acc[mt][nt][2], acc[mt][nt][3]);
                }
            }
            __syncthreads();
        }

        float gi0 = xi0, gf0 = xf0, gg0 = xgg0, go0 = xo0;
        float gi1 = xi1, gf1 = xf1, gg1 = xgg1, go1 = xo1;
        if (t > 0) {
#pragma unroll
            for (int w = 0; w < 8; w++) {
                const float* pw = part + w * RP_SZ;
                gi0 += pw[er0 * RP_STR + ej];      gf0 += pw[er0 * RP_STR + 8 + ej];
                gg0 += pw[er0 * RP_STR + 16 + ej]; go0 += pw[er0 * RP_STR + 24 + ej];
                gi1 += pw[er1 * RP_STR + ej];      gf1 += pw[er1 * RP_STR + 8 + ej];
                gg1 += pw[er1 * RP_STR + 16 + ej]; go1 += pw[er1 * RP_STR + 24 + ej];
            }
        }
        cs0 = sigf(gf0) * cs0 + sigf(gi0) * tanhf(gg0);
        cs1 = sigf(gf1) * cs1 + sigf(gi1) * tanhf(gg1);
        const float h0v = sigf(go0) * tanhf(cs0);
        const float h1v = sigf(go1) * tanhf(cs1);

        // transposed swizzled store for next step's bulk copies
        __half* hdst = hT + (size_t)((t + 1) & 1) * 65536 + c_own * 16384;
        hdst[pos_base + ((2 * er0) ^ xr_own)] = __float2half_rn(h0v);
        hdst[pos_base + ((2 * er1) ^ xr_own)] = __float2half_rn(h1v);
        if (write_all || t == TT - 1) {
            hs[((size_t)(er0 * TT + t)) * HH + n0 + ej] = __float2half_rn(h0v);
            hs[((size_t)(er1 * TT + t)) * HH + n0 + ej] = __float2half_rn(h1v);
        }

        if (t < TT - 1) grid_bar();
    }
}

// ------------------------- final MLP layer 3 ---------------------------------
__global__ void mlp3_kernel(const __half* __restrict__ z2, const float* __restrict__ W3,
                            const float* __restrict__ b3, float* __restrict__ out)
{
    __shared__ float red[8];
    const int b = blockIdx.x;
    float s = 0.f;
    for (int k = threadIdx.x; k < 512; k += 256)
        s += __half2float(z2[b * 512 + k]) * W3[k];
#pragma unroll
    for (int o = 16; o; o >>= 1) s += __shfl_down_sync(0xffffffffu, s, o);
    if ((threadIdx.x & 31) == 0) red[threadIdx.x >> 5] = s;
    __syncthreads();
    if (threadIdx.x < 8) {
        s = red[threadIdx.x];
#pragma unroll
        for (int o = 4; o; o >>= 1) s += __shfl_down_sync(0xffu, s, o);
        if (threadIdx.x == 0) out[b] = s + b3[0];
    }
}

// ------------------------- launcher ------------------------------------------
extern "C" void kernel_launch(void* const* d_in, const int* in_sizes, int n_in,
                              void* d_out, int out_size)
{
    const float* xx       = (const float*)d_in[0];
    const float* l1_Wih0  = (const float*)d_in[1];
    const float* l1_bih0  = (const float*)d_in[2];
    const float* l1_bhh0  = (const float*)d_in[3];
    const float* l1_Wih1  = (const float*)d_in[4];
    const float* l1_bih1  = (const float*)d_in[5];
    const float* l1_bhh1  = (const float*)d_in[6];
    const float* l2_Wih0  = (const float*)d_in[7];
    const float* l2_Whh0  = (const float*)d_in[8];
    const float* l2_bih0  = (const float*)d_in[9];
    const float* l2_bhh0  = (const float*)d_in[10];
    const float* l2_Wih1  = (const float*)d_in[11];
    const float* l2_Whh1  = (const float*)d_in[12];
    const float* l2_bih1  = (const float*)d_in[13];
    const float* l2_bhh1  = (const float*)d_in[14];
    const float* mlp_W1   = (const float*)d_in[15];
    const float* mlp_b1   = (const float*)d_in[16];
    const float* mlp_W2   = (const float*)d_in[17];
    const float* mlp_b2   = (const float*)d_in[18];
    const float* mlp_W3   = (const float*)d_in[19];
    const float* mlp_b3   = (const float*)d_in[20];
    float* out = (float*)d_out;

    void* p;
    cudaGetSymbolAddress(&p, g_gates); float*  gates = (float*)p;
    cudaGetSymbolAddress(&p, g_w16);   __half* w16   = (__half*)p;
    cudaGetSymbolAddress(&p, g_h1);    __half* h1    = (__half*)p;
    cudaGetSymbolAddress(&p, g_h2);    __half* h2    = (__half*)p;
    cudaGetSymbolAddress(&p, g_hT);    __half* hT    = (__half*)p;
    cudaGetSymbolAddress(&p, g_z1);    __half* z1    = (__half*)p;
    cudaGetSymbolAddress(&p, g_z2);    __half* z2    = (__half*)p;

    const int lstm1_smem = 4 * L_ST * 2;     // 81920 B
    const int gemm_smem  = 3 * G_STG * 2;    // 92160 B
    const int recur_smem = R_SMEM_B;         // 201232 B
    cudaFuncSetAttribute((const void*)gemm16_kernel<0,0>, cudaFuncAttributeMaxDynamicSharedMemorySize, gemm_smem);
    cudaFuncSetAttribute((const void*)gemm16_kernel<1,1>, cudaFuncAttributeMaxDynamicSharedMemorySize, gemm_smem);
    cudaFuncSetAttribute((const void*)lstm1_16_kernel,    cudaFuncAttributeMaxDynamicSharedMemorySize, lstm1_smem);
    cudaFuncSetAttribute((const void*)recur16_kernel,     cudaFuncAttributeMaxDynamicSharedMemorySize, recur_smem);

    const dim3 blk(256);

    // [0] fp32 -> fp16 (xx + 6 weight matrices)
    convert_kernel<<<4849664 / 256, blk>>>(xx, l1_Wih0, l1_Wih1, l2_Wih0, l2_Wih1, mlp_W1, mlp_W2);

    // [1][2] lstm1 (fused, f gate skipped)
    lstm1_16_kernel<<<dim3(HH / 128, BT / 128), blk, lstm1_smem>>>(w16 + X16_OFF, 256, w16 + W_L1A,
                                                                   l1_bih0, l1_bhh0, h1, BT, 256);
    lstm1_16_kernel<<<dim3(HH / 128, BT / 128), blk, lstm1_smem>>>(h1, HH, w16 + W_L1B,
                                                                   l1_bih1, l1_bhh1, h2, BT, HH);

    // [3][4] lstm2 layer 0 xg (split) ; [5] recurrence (profiled by ncu -s 5)
    gemm16_kernel<0,0><<<dim3(G4 / 256, 64), blk, gemm_smem>>>(h2, HH, w16 + W_L2A, l2_bih0, l2_bhh0,
                                                               gates, BT / 2, G4, HH);
    gemm16_kernel<0,0><<<dim3(G4 / 256, 64), blk, gemm_smem>>>(h2 + (size_t)(BT / 2) * HH, HH, w16 + W_L2A,
                                                               l2_bih0, l2_bhh0,
                                                               gates + (size_t)(BT / 2) * G4, BT / 2, G4, HH);
    recur16_kernel<<<NBLK_REC, blk, recur_smem>>>(gates, l2_Whh0, h1, hT, 1);

    // [6][7] lstm2 layer 1
    gemm16_kernel<0,0><<<dim3(G4 / 256, BT / 128), blk, gemm_smem>>>(h1, HH, w16 + W_L2B, l2_bih1, l2_bhh1,
                                                                     gates, BT, G4, HH);
    recur16_kernel<<<NBLK_REC, blk, recur_smem>>>(gates, l2_Whh1, h2, hT, 0);

    // [8][9][10] MLP
    gemm16_kernel<1,1><<<dim3(HH / 256, 1), blk, gemm_smem>>>(h2 + (size_t)(TT - 1) * HH, (long long)TT * HH,
                                                              w16 + W_M1, mlp_b1, nullptr, z1, BB, HH, HH);
    gemm16_kernel<1,1><<<dim3((HH / 2) / 256, 1), blk, gemm_smem>>>(z1, HH, w16 + W_M2, mlp_b2, nullptr,
                                                                    z2, BB, HH / 2, HH);
    mlp3_kernel<<<BB, blk>>>(z2, mlp_W3, mlp_b3, out);
}

// round 6
// speedup vs baseline: 1.5561x; 1.5561x over previous
#include <cuda_runtime.h>
#include <cuda_fp16.h>
#include <cstdint>
#include <cstddef>

#define HH 1024
#define TT 256
#define BB 64
#define BT (BB*TT)       /* 16384 */
#define G4 (4*HH)        /* 4096 */
#define NBLK_REC 128

/* fp16 GEMM tile constants (stride in halves) */
#define HSTR 40
#define L_ST (256*HSTR)             /* lstm1 stage halves (A128+B128) */
#define G_AT (128*HSTR)             /* gemm A region halves */
#define G_STG (384*HSTR)            /* gemm stage halves (A128+B256)  */

/* recurrence smem byte offsets */
#define R_WS_B   0                  /* Ws: 32*1032 halves = 66048 B   */
#define R_TB_B   66048              /* tb: 2 chunks x 65536 B         */
#define R_MBAR_B 197120
#define R_SMEM_B 197136
#define RP_STR 34
#define RP_SZ  (64*RP_STR)          /* 2176 floats per warp partial   */

/* fp16 scratch offsets (halves) */
#define X16_OFF  0u
#define W_L1A    4194304u
#define W_L1B    5242880u
#define W_L2A    9437184u
#define W_L2B    13631488u
#define W_M1     17825792u
#define W_M2     18874368u
#define W16_TOT  19398656u

// ------------------------- scratch (device globals) --------------------------
__device__ __align__(256) float  g_gates[(size_t)BT * G4];   // fp32 xg scratch
__device__ __align__(256) __half g_w16[W16_TOT];             // converted x + weights
__device__ __align__(256) __half g_h1[(size_t)BT * HH];
__device__ __align__(256) __half g_h2[(size_t)BT * HH];
__device__ __align__(256) __half g_hT[2 * HH * BB];          // transposed swizzled h
__device__ __align__(256) __half g_z1[BB * HH];
__device__ __align__(256) __half g_z2[BB * (HH/2)];
__device__ volatile unsigned g_cnt = 0;
__device__ volatile unsigned g_sense = 0;

// ------------------------- helpers ------------------------------------------
__device__ __forceinline__ uint32_t ld_u32h(const __half* p) {
    return *(const uint32_t*)p;
}
__device__ __forceinline__ void mma_fp16(float c[4],
                                         uint32_t a0, uint32_t a1, uint32_t a2, uint32_t a3,
                                         uint32_t b0, uint32_t b1) {
    asm volatile(
        "mma.sync.aligned.m16n8k16.row.col.f32.f16.f16.f32 "
        "{%0,%1,%2,%3}, {%4,%5,%6,%7}, {%8,%9}, {%0,%1,%2,%3};"
        : "+f"(c[0]), "+f"(c[1]), "+f"(c[2]), "+f"(c[3])
        : "r"(a0), "r"(a1), "r"(a2), "r"(a3), "r"(b0), "r"(b1));
}
__device__ __forceinline__ float sigf(float x) { return 1.0f / (1.0f + expf(-x)); }

__device__ __forceinline__ void cp16(uint32_t dsh, const void* src) {
    asm volatile("cp.async.cg.shared.global [%0], [%1], 16;" :: "r"(dsh), "l"(src));
}
__device__ __forceinline__ void cp_commit() { asm volatile("cp.async.commit_group;"); }

__device__ __forceinline__ void mbar_init(uint32_t mbar, uint32_t cnt) {
    asm volatile("mbarrier.init.shared.b64 [%0], %1;" :: "r"(mbar), "r"(cnt) : "memory");
}
__device__ __forceinline__ void mbar_expect(uint32_t mbar, uint32_t bytes) {
    asm volatile("mbarrier.arrive.expect_tx.shared.b64 _, [%0], %1;" :: "r"(mbar), "r"(bytes) : "memory");
}
__device__ __forceinline__ void bulk_g2s(uint32_t dst, const void* src, uint32_t bytes, uint32_t mbar) {
    asm volatile("cp.async.bulk.shared::cluster.global.mbarrier::complete_tx::bytes [%0], [%1], %2, [%3];"
                 :: "r"(dst), "l"(src), "r"(bytes), "r"(mbar) : "memory");
}
__device__ __forceinline__ void mbar_wait(uint32_t mbar, uint32_t parity) {
    uint32_t done;
    asm volatile(
        "{\n\t.reg .pred p;\n\t"
        "mbarrier.try_wait.parity.acquire.cta.shared::cta.b64 p, [%1], %2;\n\t"
        "selp.b32 %0, 1, 0, p;\n\t}"
        : "=r"(done) : "r"(mbar), "r"(parity) : "memory");
    if (!done) {
        asm volatile(
            "{\n\t.reg .pred P1;\n\t"
            "WL_%=:\n\t"
            "mbarrier.try_wait.parity.acquire.cta.shared::cta.b64 P1, [%0], %1, 0x989680;\n\t"
            "@P1 bra.uni WD_%=;\n\t"
            "bra.uni WL_%=;\n\t"
            "WD_%=:\n\t}"
            :: "r"(mbar), "r"(parity) : "memory");
    }
}

// =============================================================================
// fp32 -> fp16 conversion of xx + 6 weight matrices (one launch)
// =============================================================================
__global__ void convert_kernel(const float* __restrict__ xx,
                               const float* __restrict__ w0, const float* __restrict__ w1,
                               const float* __restrict__ w2, const float* __restrict__ w3,
                               const float* __restrict__ w4, const float* __restrict__ w5)
{
    const uint32_t i4 = blockIdx.x * blockDim.x + threadIdx.x;   // float4 index
    const float* src; uint32_t base4;
    if      (i4 < 1048576u) { src = xx; base4 = 0u; }
    else if (i4 < 1310720u) { src = w0; base4 = 1048576u; }
    else if (i4 < 2359296u) { src = w1; base4 = 1310720u; }
    else if (i4 < 3407872u) { src = w2; base4 = 2359296u; }
    else if (i4 < 4456448u) { src = w3; base4 = 3407872u; }
    else if (i4 < 4718592u) { src = w4; base4 = 4456448u; }
    else                    { src = w5; base4 = 4718592u; }
    const float4 v = ((const float4*)src)[i4 - base4];
    __half2* dst = (__half2*)(g_w16 + (size_t)i4 * 4);
    dst[0] = __floats2half2_rn(v.x, v.y);
    dst[1] = __floats2half2_rn(v.z, v.w);
}

// =============================================================================
// fp16 GEMM: C = A @ W^T (+bias, +ReLU). BM=128, BN=256, BK=32, 3-stage.
// =============================================================================
template<int RELU, int HOUT>
__launch_bounds__(256, 1)
__global__ void gemm16_kernel(const __half* __restrict__ A, long long asr,
                              const __half* __restrict__ W,
                              const float* __restrict__ b1p, const float* __restrict__ b2p,
                              void* __restrict__ Cv, int M, int N, int K)
{
    extern __shared__ __half smh[];
    const int tid = threadIdx.x, lane = tid & 31, warp = tid >> 5;
    const int wm = warp >> 2, wn = warp & 3;
    const int g = lane >> 2, q = lane & 3;
    const int mb = blockIdx.y * 128, nb = blockIdx.x * 256;

    float acc[4][8][4];
#pragma unroll
    for (int a = 0; a < 4; a++)
#pragma unroll
        for (int b = 0; b < 8; b++)
#pragma unroll
            for (int c = 0; c < 4; c++) acc[a][b][c] = 0.0f;

    const uint32_t smb = (uint32_t)__cvta_generic_to_shared(smh);
    const __half* aptr[2]; uint32_t adst[2];
#pragma unroll
    for (int i = 0; i < 2; i++) {
        const int slot = tid + i * 256;
        const int row = slot >> 2, kc = (slot & 3) * 8;
        int gr = mb + row; if (gr > M - 1) gr = M - 1;
        aptr[i] = A + (size_t)gr * asr + kc;
        adst[i] = smb + (uint32_t)((row * HSTR + kc) * 2);
    }
    const __half* bptr[4]; uint32_t bdst[4];
#pragma unroll
    for (int i = 0; i < 4; i++) {
        const int slot = tid + i * 256;
        const int row = slot >> 2, kc = (slot & 3) * 8;
        bptr[i] = W + (size_t)(nb + row) * K + kc;
        bdst[i] = smb + (uint32_t)((G_AT + row * HSTR + kc) * 2);
    }

    const int KT = K >> 5;
    auto issue = [&](int kt) {
        const uint32_t so = (uint32_t)((kt % 3) * G_STG * 2);
        const int koff = kt * 32;
#pragma unroll
        for (int i = 0; i < 2; i++) cp16(adst[i] + so, aptr[i] + koff);
#pragma unroll
        for (int i = 0; i < 4; i++) cp16(bdst[i] + so, bptr[i] + koff);
        cp_commit();
    };

    issue(0); if (KT > 1) issue(1);

    for (int kt = 0; kt < KT; ++kt) {
        if (kt < KT - 1) asm volatile("cp.async.wait_group 1;");
        else             asm volatile("cp.async.wait_group 0;");
        __syncthreads();
        if (kt + 2 < KT) issue(kt + 2);

        const __half* Ab = smh + (kt % 3) * G_STG;
        const __half* Bb = Ab + G_AT;
#pragma unroll
        for (int kk = 0; kk < 32; kk += 16) {
            uint32_t af[4][4], bfr[8][2];
#pragma unroll
            for (int mt = 0; mt < 4; mt++) {
                const int r = wm * 64 + mt * 16 + g;
                af[mt][0] = ld_u32h(Ab + r * HSTR + kk + 2 * q);
                af[mt][1] = ld_u32h(Ab + (r + 8) * HSTR + kk + 2 * q);
                af[mt][2] = ld_u32h(Ab + r * HSTR + kk + 2 * q + 8);
                af[mt][3] = ld_u32h(Ab + (r + 8) * HSTR + kk + 2 * q + 8);
            }
#pragma unroll
            for (int nt = 0; nt < 8; nt++) {
                const int n = wn * 64 + nt * 8 + g;
                bfr[nt][0] = ld_u32h(Bb + n * HSTR + kk + 2 * q);
                bfr[nt][1] = ld_u32h(Bb + n * HSTR + kk + 2 * q + 8);
            }
#pragma unroll
            for (int mt = 0; mt < 4; mt++)
#pragma unroll
                for (int nt = 0; nt < 8; nt++)
                    mma_fp16(acc[mt][nt], af[mt][0], af[mt][1], af[mt][2], af[mt][3],
                             bfr[nt][0], bfr[nt][1]);
        }
    }

#pragma unroll
    for (int mt = 0; mt < 4; mt++) {
#pragma unroll
        for (int nt = 0; nt < 8; nt++) {
            const int row0 = mb + wm * 64 + mt * 16 + g;
            const int col  = nb + wn * 64 + nt * 8 + 2 * q;
            const float b0v = (b1p ? b1p[col]     : 0.f) + (b2p ? b2p[col]     : 0.f);
            const float b1v = (b1p ? b1p[col + 1] : 0.f) + (b2p ? b2p[col + 1] : 0.f);
            float v0 = acc[mt][nt][0] + b0v, v1 = acc[mt][nt][1] + b1v;
            float v2 = acc[mt][nt][2] + b0v, v3 = acc[mt][nt][3] + b1v;
            if (RELU) {
                v0 = fmaxf(v0, 0.f); v1 = fmaxf(v1, 0.f);
                v2 = fmaxf(v2, 0.f); v3 = fmaxf(v3, 0.f);
            }
            if (HOUT) {
                __half* C = (__half*)Cv;
                if (row0 < M)     *(__half2*)(C + (size_t)row0 * N + col)       = __floats2half2_rn(v0, v1);
                if (row0 + 8 < M) *(__half2*)(C + (size_t)(row0 + 8) * N + col) = __floats2half2_rn(v2, v3);
            } else {
                float* C = (float*)Cv;
                if (row0 < M)     *(float2*)(C + (size_t)row0 * N + col)       = make_float2(v0, v1);
                if (row0 + 8 < M) *(float2*)(C + (size_t)(row0 + 8) * N + col) = make_float2(v2, v3);
            }
        }
    }
}

// =============================================================================
// fused lstm1 (fp16): h = sig(o)*tanh(sig(i)*tanh(g)); f gate skipped.
// =============================================================================
__launch_bounds__(256, 1)
__global__ void lstm1_16_kernel(const __half* __restrict__ A, long long asr,
                                const __half* __restrict__ W,
                                const float* __restrict__ bih, const float* __restrict__ bhh,
                                __half* __restrict__ Hout, int M, int K)
{
    extern __shared__ __half smh[];
    const int tid = threadIdx.x, lane = tid & 31, warp = tid >> 5;
    const int wm = warp >> 2, wn = warp & 3;
    const int g = lane >> 2, q = lane & 3;
    const int mb = blockIdx.y * 128, nb = blockIdx.x * 128;

    const uint32_t smb = (uint32_t)__cvta_generic_to_shared(smh);

    const __half* aptr[2]; uint32_t adst[2];
#pragma unroll
    for (int i = 0; i < 2; i++) {
        const int slot = tid + i * 256;
        const int row = slot >> 2, kc = (slot & 3) * 8;
        int gr = mb + row; if (gr > M - 1) gr = M - 1;
        aptr[i] = A + (size_t)gr * asr + kc;
        adst[i] = smb + (uint32_t)((row * HSTR + kc) * 2);
    }
    uint32_t bdst[2]; int brow[2], bkc[2];
#pragma unroll
    for (int i = 0; i < 2; i++) {
        const int slot = tid + i * 256;
        brow[i] = slot >> 2; bkc[i] = (slot & 3) * 8;
        bdst[i] = smb + (uint32_t)(((128 + brow[i]) * HSTR + bkc[i]) * 2);
    }

    const int KT = K >> 5;
    float keep[4][4][4];
    const int gset[3] = {0, 2, 3};

#pragma unroll 1
    for (int ph = 0; ph < 3; ++ph) {
        const int gate = gset[ph];
        const __half* Wb = W + ((size_t)(gate * HH + nb)) * K;

        float acc[4][4][4];
#pragma unroll
        for (int a = 0; a < 4; a++)
#pragma unroll
            for (int b = 0; b < 4; b++)
#pragma unroll
                for (int c = 0; c < 4; c++) acc[a][b][c] = 0.0f;

        auto issue = [&](int kt) {
            const int koff = kt * 32;
            const uint32_t so = (uint32_t)((kt & 3) * L_ST * 2);
#pragma unroll
            for (int i = 0; i < 2; i++) cp16(adst[i] + so, aptr[i] + koff);
#pragma unroll
            for (int i = 0; i < 2; i++) cp16(bdst[i] + so, Wb + (size_t)brow[i] * K + bkc[i] + koff);
            cp_commit();
        };

        const int pre = KT < 3 ? KT : 3;
        for (int s = 0; s < pre; ++s) issue(s);

        for (int kt = 0; kt < KT; ++kt) {
            if (kt < KT - 2)       asm volatile("cp.async.wait_group 2;");
            else if (kt == KT - 2) asm volatile("cp.async.wait_group 1;");
            else                   asm volatile("cp.async.wait_group 0;");
            __syncthreads();
            if (kt + 3 < KT) issue(kt + 3);

            const __half* Ab = smh + (kt & 3) * L_ST;
            const __half* Bb = Ab + 128 * HSTR;
#pragma unroll
            for (int kk = 0; kk < 32; kk += 16) {
                uint32_t af[4][4], bfr[4][2];
#pragma unroll
                for (int mt = 0; mt < 4; mt++) {
                    const int r = wm * 64 + mt * 16 + g;
                    af[mt][0] = ld_u32h(Ab + r * HSTR + kk + 2 * q);
                    af[mt][1] = ld_u32h(Ab + (r + 8) * HSTR + kk + 2 * q);
                    af[mt][2] = ld_u32h(Ab + r * HSTR + kk + 2 * q + 8);
                    af[mt][3] = ld_u32h(Ab + (r + 8) * HSTR + kk + 2 * q + 8);
                }
#pragma unroll
                for (int nt = 0; nt < 4; nt++) {
                    const int n = wn * 32 + nt * 8 + g;
                    bfr[nt][0] = ld_u32h(Bb + n * HSTR + kk + 2 * q);
                    bfr[nt][1] = ld_u32h(Bb + n * HSTR + kk + 2 * q + 8);
                }
#pragma unroll
                for (int mt = 0; mt < 4; mt++)
#pragma unroll
                    for (int nt = 0; nt < 4; nt++)
                        mma_fp16(acc[mt][nt], af[mt][0], af[mt][1], af[mt][2], af[mt][3],
                                 bfr[nt][0], bfr[nt][1]);
            }
        }
        __syncthreads();

#pragma unroll
        for (int mt = 0; mt < 4; mt++) {
#pragma unroll
            for (int nt = 0; nt < 4; nt++) {
                const int gcol = gate * HH + nb + wn * 32 + nt * 8 + 2 * q;
                const float b0 = bih[gcol] + bhh[gcol];
                const float b1 = bih[gcol + 1] + bhh[gcol + 1];
                if (ph == 0) {
                    keep[mt][nt][0] = sigf(acc[mt][nt][0] + b0);
                    keep[mt][nt][1] = sigf(acc[mt][nt][1] + b1);
                    keep[mt][nt][2] = sigf(acc[mt][nt][2] + b0);
                    keep[mt][nt][3] = sigf(acc[mt][nt][3] + b1);
                } else if (ph == 1) {
                    keep[mt][nt][0] *= tanhf(acc[mt][nt][0] + b0);
                    keep[mt][nt][1] *= tanhf(acc[mt][nt][1] + b1);
                    keep[mt][nt][2] *= tanhf(acc[mt][nt][2] + b0);
                    keep[mt][nt][3] *= tanhf(acc[mt][nt][3] + b1);
                } else {
                    const int row0 = mb + wm * 64 + mt * 16 + g;
                    const int colh = nb + wn * 32 + nt * 8 + 2 * q;
                    const float v0 = sigf(acc[mt][nt][0] + b0) * tanhf(keep[mt][nt][0]);
                    const float v1 = sigf(acc[mt][nt][1] + b1) * tanhf(keep[mt][nt][1]);
                    const float v2 = sigf(acc[mt][nt][2] + b0) * tanhf(keep[mt][nt][2]);
                    const float v3 = sigf(acc[mt][nt][3] + b1) * tanhf(keep[mt][nt][3]);
                    if (row0 < M)     *(__half2*)(Hout + (size_t)row0 * HH + colh)       = __floats2half2_rn(v0, v1);
                    if (row0 + 8 < M) *(__half2*)(Hout + (size_t)(row0 + 8) * HH + colh) = __floats2half2_rn(v2, v3);
                }
            }
        }
    }
}

// ------------------------- grid barrier --------------------------------------
__device__ __forceinline__ void grid_bar()
{
    __threadfence();
    __syncthreads();
    if (threadIdx.x == 0) {
        const unsigned gen = g_sense;
        const unsigned arrived = atomicAdd((unsigned*)&g_cnt, 1u);
        if (arrived == NBLK_REC - 1u) {
            g_cnt = 0;
            __threadfence();
            atomicAdd((unsigned*)&g_sense, 1u);
        } else {
            while (g_sense == gen) { __nanosleep(16); }
        }
        __threadfence();
    }
    __syncthreads();
}

// =============================================================================
// RECURRENT LSTM LAYER — restructured pipeline
//
// Per step: thread0 issues BOTH 64KB h chunks up-front (TMA). Warps 0-3 bind
// to chunk0 (k<512), warps 4-7 to chunk1: each warp does exactly ONE
// mbar_wait and no inter-chunk syncthreads. fp32 partials (8-way K-split)
// reduced in SMEM (2 syncthreads/step). xg prefetched under the mma.
// =============================================================================
__launch_bounds__(256, 1)
__global__ void recur16_kernel(const float* __restrict__ xg,   // [BT, 4096] fp32
                               const float* __restrict__ Whh,  // [4096, 1024] fp32
                               __half* __restrict__ hs,        // [BT, 1024]
                               __half* __restrict__ hT,        // [2][65536] swizzled
                               int write_all)
{
    extern __shared__ char smc[];
    __half* Ws  = (__half*)(smc + R_WS_B);     // [32][1032]
    __half* tb  = (__half*)(smc + R_TB_B);     // 2 x 32768 halves
    float* part = (float*)(smc + R_TB_B);      // overlay: 8 x [64][34] f32

    const uint32_t smb = (uint32_t)__cvta_generic_to_shared(smc);
    const uint32_t tb_sh = smb + R_TB_B;
    const uint32_t mb0 = smb + R_MBAR_B, mb1 = mb0 + 8;

    const int tid = threadIdx.x, lane = tid & 31;
    const int wk = tid >> 5;                 // K-split warp index 0..7
    const int g = lane >> 2, q = lane & 3;
    const int n0 = blockIdx.x * 8;
    const int chn = wk >> 2;                 // this warp's chunk (0 or 1)
    const uint32_t mb_my = chn ? mb1 : mb0;

    if (tid == 0) { mbar_init(mb0, 1); mbar_init(mb1, 1); }

    // Whh slab fp16: packed row c = gate*8 + j  <-  Whh[gate*HH + n0 + j]
#pragma unroll 1
    for (int c = 0; c < 32; c++) {
        const int gg = c >> 3, j = c & 7;
        const float4 v = *(const float4*)(Whh + ((size_t)(gg * HH + n0 + j)) * HH + tid * 4);
        __half* d = Ws + c * 1032 + tid * 4;
        d[0] = __float2half_rn(v.x); d[1] = __float2half_rn(v.y);
        d[2] = __float2half_rn(v.z); d[3] = __float2half_rn(v.w);
    }
    __syncthreads();

    const __half* tb_c = tb + chn * 32768;   // warp's chunk buffer

    // elementwise / h-store mapping
    const int er0 = tid >> 3, ej = tid & 7, er1 = er0 + 32;
    const int k_own = n0 + ej;
    const int s_own = k_own >> 1;                    // global segment 0..511
    const int c_own = s_own >> 8;
    const int pos_base = (s_own & 255) * 128 + (k_own & 1);
    const int xr_own = 16 * (s_own & 3);
    float cs0 = 0.f, cs1 = 0.f;

    for (int t = 0; t < TT; t++) {
        const __half* hsrc = hT + (size_t)(t & 1) * 65536;

        // issue both 64KB chunks immediately
        if (t > 0 && tid == 0) {
            mbar_expect(mb0, 65536);
            bulk_g2s(tb_sh, hsrc, 65536, mb0);
            mbar_expect(mb1, 65536);
            bulk_g2s(tb_sh + 65536u, hsrc + 32768, 65536, mb1);
        }

        // xg prefetch (overlaps copy + mma)
        const size_t x0 = ((size_t)(er0 * TT + t)) * G4 + n0 + ej;
        const size_t x1 = ((size_t)(er1 * TT + t)) * G4 + n0 + ej;
        const float xi0 = xg[x0], xf0 = xg[x0 + 1024], xgg0 = xg[x0 + 2048], xo0 = xg[x0 + 3072];
        const float xi1 = xg[x1], xf1 = xg[x1 + 1024], xgg1 = xg[x1 + 2048], xo1 = xg[x1 + 3072];

        if (t > 0) {
            float acc[4][4][4];
#pragma unroll
            for (int a = 0; a < 4; a++)
#pragma unroll
                for (int b = 0; b < 4; b++)
#pragma unroll
                    for (int cc = 0; cc < 4; cc++) acc[a][b][cc] = 0.0f;

            mbar_wait(mb_my, (t - 1) & 1u);

            // warp wk: k in [wk*128, wk*128+128) -> 8 k-iters of 16
#pragma unroll
            for (int kk = 0; kk < 8; ++kk) {
                const int seg_local = (wk & 3) * 64 + kk * 8 + q;
                const int xr = 16 * (seg_local & 3);
                const __half* p0 = tb_c + seg_local * 128;
                const __half* p1 = p0 + 512;
                uint32_t a[4][4];
#pragma unroll
                for (int mt = 0; mt < 4; mt++) {
                    const int r = mt * 16 + g;
                    a[mt][0] = ld_u32h(p0 + ((2 * r) ^ xr));
                    a[mt][1] = ld_u32h(p0 + ((2 * (r + 8)) ^ xr));
                    a[mt][2] = ld_u32h(p1 + ((2 * r) ^ xr));
                    a[mt][3] = ld_u32h(p1 + ((2 * (r + 8)) ^ xr));
                }
                const int kglob = wk * 128 + kk * 16 + 2 * q;
                uint32_t bfr[4][2];
#pragma unroll
                for (int nt = 0; nt < 4; nt++) {
                    const int n = nt * 8 + g;
                    bfr[nt][0] = ld_u32h(Ws + n * 1032 + kglob);
                    bfr[nt][1] = ld_u32h(Ws + n * 1032 + kglob + 8);
                }
#pragma unroll
                for (int mt = 0; mt < 4; mt++)
#pragma unroll
                    for (int nt = 0; nt < 4; nt++)
                        mma_fp16(acc[mt][nt], a[mt][0], a[mt][1], a[mt][2], a[mt][3],
                                 bfr[nt][0], bfr[nt][1]);
            }

            __syncthreads();   // all chunk reads done before partial overlay

            float* pw = part + wk * RP_SZ;
#pragma unroll
            for (int mt = 0; mt < 4; mt++) {
#pragma unroll
                for (int nt = 0; nt < 4; nt++) {
                    const int r = mt * 16 + g;
                    const int cc = nt * 8 + 2 * q;
                    *(float2*)(pw + r * RP_STR + cc)       = make_float2(acc[mt][nt][0], acc[mt][nt][1]);
                    *(float2*)(pw + (r + 8) * RP_STR + cc) = make_float2(acc[mt][nt][2], acc[mt][nt][3]);
                }
            }
            __syncthreads();
        }

        float gi0 = xi0, gf0 = xf0, gg0 = xgg0, go0 = xo0;
        float gi1 = xi1, gf1 = xf1, gg1 = xgg1, go1 = xo1;
        if (t > 0) {
#pragma unroll
            for (int w = 0; w < 8; w++) {
                const float* pw = part + w * RP_SZ;
                gi0 += pw[er0 * RP_STR + ej];      gf0 += pw[er0 * RP_STR + 8 + ej];
                gg0 += pw[er0 * RP_STR + 16 + ej]; go0 += pw[er0 * RP_STR + 24 + ej];
                gi1 += pw[er1 * RP_STR + ej];      gf1 += pw[er1 * RP_STR + 8 + ej];
                gg1 += pw[er1 * RP_STR + 16 + ej]; go1 += pw[er1 * RP_STR + 24 + ej];
            }
        }
        cs0 = sigf(gf0) * cs0 + sigf(gi0) * tanhf(gg0);
        cs1 = sigf(gf1) * cs1 + sigf(gi1) * tanhf(gg1);
        const float h0v = sigf(go0) * tanhf(cs0);
        const float h1v = sigf(go1) * tanhf(cs1);

        // transposed swizzled store for next step's bulk copies
        __half* hdst = hT + (size_t)((t + 1) & 1) * 65536 + c_own * 32768;
        hdst[pos_base + ((2 * er0) ^ xr_own)] = __float2half_rn(h0v);
        hdst[pos_base + ((2 * er1) ^ xr_own)] = __float2half_rn(h1v);
        if (write_all || t == TT - 1) {
            hs[((size_t)(er0 * TT + t)) * HH + n0 + ej] = __float2half_rn(h0v);
            hs[((size_t)(er1 * TT + t)) * HH + n0 + ej] = __float2half_rn(h1v);
        }

        if (t < TT - 1) grid_bar();
    }
}

// ------------------------- final MLP layer 3 ---------------------------------
__global__ void mlp3_kernel(const __half* __restrict__ z2, const float* __restrict__ W3,
                            const float* __restrict__ b3, float* __restrict__ out)
{
    __shared__ float red[8];
    const int b = blockIdx.x;
    float s = 0.f;
    for (int k = threadIdx.x; k < 512; k += 256)
        s += __half2float(z2[b * 512 + k]) * W3[k];
#pragma unroll
    for (int o = 16; o; o >>= 1) s += __shfl_down_sync(0xffffffffu, s, o);
    if ((threadIdx.x & 31) == 0) red[threadIdx.x >> 5] = s;
    __syncthreads();
    if (threadIdx.x < 8) {
        s = red[threadIdx.x];
#pragma unroll
        for (int o = 4; o; o >>= 1) s += __shfl_down_sync(0xffu, s, o);
        if (threadIdx.x == 0) out[b] = s + b3[0];
    }
}

// ------------------------- launcher ------------------------------------------
extern "C" void kernel_launch(void* const* d_in, const int* in_sizes, int n_in,
                              void* d_out, int out_size)
{
    const float* xx       = (const float*)d_in[0];
    const float* l1_Wih0  = (const float*)d_in[1];
    const float* l1_bih0  = (const float*)d_in[2];
    const float* l1_bhh0  = (const float*)d_in[3];
    const float* l1_Wih1  = (const float*)d_in[4];
    const float* l1_bih1  = (const float*)d_in[5];
    const float* l1_bhh1  = (const float*)d_in[6];
    const float* l2_Wih0  = (const float*)d_in[7];
    const float* l2_Whh0  = (const float*)d_in[8];
    const float* l2_bih0  = (const float*)d_in[9];
    const float* l2_bhh0  = (const float*)d_in[10];
    const float* l2_Wih1  = (const float*)d_in[11];
    const float* l2_Whh1  = (const float*)d_in[12];
    const float* l2_bih1  = (const float*)d_in[13];
    const float* l2_bhh1  = (const float*)d_in[14];
    const float* mlp_W1   = (const float*)d_in[15];
    const float* mlp_b1   = (const float*)d_in[16];
    const float* mlp_W2   = (const float*)d_in[17];
    const float* mlp_b2   = (const float*)d_in[18];
    const float* mlp_W3   = (const float*)d_in[19];
    const float* mlp_b3   = (const float*)d_in[20];
    float* out = (float*)d_out;

    void* p;
    cudaGetSymbolAddress(&p, g_gates); float*  gates = (float*)p;
    cudaGetSymbolAddress(&p, g_w16);   __half* w16   = (__half*)p;
    cudaGetSymbolAddress(&p, g_h1);    __half* h1    = (__half*)p;
    cudaGetSymbolAddress(&p, g_h2);    __half* h2    = (__half*)p;
    cudaGetSymbolAddress(&p, g_hT);    __half* hT    = (__half*)p;
    cudaGetSymbolAddress(&p, g_z1);    __half* z1    = (__half*)p;
    cudaGetSymbolAddress(&p, g_z2);    __half* z2    = (__half*)p;

    const int lstm1_smem = 4 * L_ST * 2;     // 81920 B
    const int gemm_smem  = 3 * G_STG * 2;    // 92160 B
    const int recur_smem = R_SMEM_B;         // 197136 B
    cudaFuncSetAttribute((const void*)gemm16_kernel<0,0>, cudaFuncAttributeMaxDynamicSharedMemorySize, gemm_smem);
    cudaFuncSetAttribute((const void*)gemm16_kernel<1,1>, cudaFuncAttributeMaxDynamicSharedMemorySize, gemm_smem);
    cudaFuncSetAttribute((const void*)lstm1_16_kernel,    cudaFuncAttributeMaxDynamicSharedMemorySize, lstm1_smem);
    cudaFuncSetAttribute((const void*)recur16_kernel,     cudaFuncAttributeMaxDynamicSharedMemorySize, recur_smem);

    const dim3 blk(256);

    // [0] fp32 -> fp16 (xx + 6 weight matrices)
    convert_kernel<<<4849664 / 256, blk>>>(xx, l1_Wih0, l1_Wih1, l2_Wih0, l2_Wih1, mlp_W1, mlp_W2);

    // [1][2] lstm1 (fused, f gate skipped)
    lstm1_16_kernel<<<dim3(HH / 128, BT / 128), blk, lstm1_smem>>>(w16 + X16_OFF, 256, w16 + W_L1A,
                                                                   l1_bih0, l1_bhh0, h1, BT, 256);
    lstm1_16_kernel<<<dim3(HH / 128, BT / 128), blk, lstm1_smem>>>(h1, HH, w16 + W_L1B,
                                                                   l1_bih1, l1_bhh1, h2, BT, HH);

    // [3][4] lstm2 layer 0 xg (split) ; [5] recurrence (profiled by ncu -s 5)
    gemm16_kernel<0,0><<<dim3(G4 / 256, 64), blk, gemm_smem>>>(h2, HH, w16 + W_L2A, l2_bih0, l2_bhh0,
                                                               gates, BT / 2, G4, HH);
    gemm16_kernel<0,0><<<dim3(G4 / 256, 64), blk, gemm_smem>>>(h2 + (size_t)(BT / 2) * HH, HH, w16 + W_L2A,
                                                               l2_bih0, l2_bhh0,
                                                               gates + (size_t)(BT / 2) * G4, BT / 2, G4, HH);
    recur16_kernel<<<NBLK_REC, blk, recur_smem>>>(gates, l2_Whh0, h1, hT, 1);

    // [6][7] lstm2 layer 1
    gemm16_kernel<0,0><<<dim3(G4 / 256, BT / 128), blk, gemm_smem>>>(h1, HH, w16 + W_L2B, l2_bih1, l2_bhh1,
                                                                     gates, BT, G4, HH);
    recur16_kernel<<<NBLK_REC, blk, recur_smem>>>(gates, l2_Whh1, h2, hT, 0);

    // [8][9][10] MLP
    gemm16_kernel<1,1><<<dim3(HH / 256, 1), blk, gemm_smem>>>(h2 + (size_t)(TT - 1) * HH, (long long)TT * HH,
                                                              w16 + W_M1, mlp_b1, nullptr, z1, BB, HH, HH);
    gemm16_kernel<1,1><<<dim3((HH / 2) / 256, 1), blk, gemm_smem>>>(z1, HH, w16 + W_M2, mlp_b2, nullptr,
                                                                    z2, BB, HH / 2, HH);
    mlp3_kernel<<<BB, blk>>>(z2, mlp_W3, mlp_b3, out);
}

// round 7
// speedup vs baseline: 1.6931x; 1.0880x over previous
#include <cuda_runtime.h>
#include <cuda_fp16.h>
#include <cstdint>
#include <cstddef>

#define HH 1024
#define TT 256
#define BB 64
#define BT (BB*TT)       /* 16384 */
#define G4 (4*HH)        /* 4096 */

/* fp16 GEMM tile constants (stride in halves) */
#define HSTR 40
#define L_ST (256*HSTR)             /* lstm1 stage halves (A128+B128) */
#define G_AT (128*HSTR)             /* gemm A region halves */
#define G_STG (384*HSTR)            /* gemm stage halves (A128+B256)  */

/* recurrence smem byte offsets (batch-split edition) */
#define R2_WS_B   0                 /* Ws: 64*1032 halves = 132096 B  */
#define R2_TB_B   132096            /* tb: 2 x 32768 B / partials     */
#define R2_MBAR_B 199680
#define R2_SMEM_B 199696
#define P2_STR 66
#define P2_SZ  (32*P2_STR)          /* 2112 floats per warp partial   */

/* fp16 scratch offsets (halves) */
#define X16_OFF  0u
#define W_L1A    4194304u
#define W_L1B    5242880u
#define W_L2A    9437184u
#define W_L2B    13631488u
#define W_M1     17825792u
#define W_M2     18874368u
#define W16_TOT  19398656u

// ------------------------- scratch (device globals) --------------------------
__device__ __align__(256) float  g_gates[(size_t)BT * G4];   // fp32 xg scratch
__device__ __align__(256) __half g_w16[W16_TOT];             // converted x + weights
__device__ __align__(256) __half g_h1[(size_t)BT * HH];
__device__ __align__(256) __half g_h2[(size_t)BT * HH];
__device__ __align__(256) __half g_hT[4 * 32768];            // [group][parity][32768]
__device__ __align__(256) __half g_z1[BB * HH];
__device__ __align__(256) __half g_z2[BB * (HH/2)];
__device__ volatile unsigned g_cnt2[2]   = {0, 0};
__device__ volatile unsigned g_sense2[2] = {0, 0};

// ------------------------- helpers ------------------------------------------
__device__ __forceinline__ uint32_t ld_u32h(const __half* p) {
    return *(const uint32_t*)p;
}
__device__ __forceinline__ void mma_fp16(float c[4],
                                         uint32_t a0, uint32_t a1, uint32_t a2, uint32_t a3,
                                         uint32_t b0, uint32_t b1) {
    asm volatile(
        "mma.sync.aligned.m16n8k16.row.col.f32.f16.f16.f32 "
        "{%0,%1,%2,%3}, {%4,%5,%6,%7}, {%8,%9}, {%0,%1,%2,%3};"
        : "+f"(c[0]), "+f"(c[1]), "+f"(c[2]), "+f"(c[3])
        : "r"(a0), "r"(a1), "r"(a2), "r"(a3), "r"(b0), "r"(b1));
}
__device__ __forceinline__ float sigf(float x) { return 1.0f / (1.0f + expf(-x)); }

__device__ __forceinline__ void cp16(uint32_t dsh, const void* src) {
    asm volatile("cp.async.cg.shared.global [%0], [%1], 16;" :: "r"(dsh), "l"(src));
}
__device__ __forceinline__ void cp_commit() { asm volatile("cp.async.commit_group;"); }

__device__ __forceinline__ void mbar_init(uint32_t mbar, uint32_t cnt) {
    asm volatile("mbarrier.init.shared.b64 [%0], %1;" :: "r"(mbar), "r"(cnt) : "memory");
}
__device__ __forceinline__ void mbar_expect(uint32_t mbar, uint32_t bytes) {
    asm volatile("mbarrier.arrive.expect_tx.shared.b64 _, [%0], %1;" :: "r"(mbar), "r"(bytes) : "memory");
}
__device__ __forceinline__ void bulk_g2s(uint32_t dst, const void* src, uint32_t bytes, uint32_t mbar) {
    asm volatile("cp.async.bulk.shared::cluster.global.mbarrier::complete_tx::bytes [%0], [%1], %2, [%3];"
                 :: "r"(dst), "l"(src), "r"(bytes), "r"(mbar) : "memory");
}
__device__ __forceinline__ void mbar_wait(uint32_t mbar, uint32_t parity) {
    uint32_t done;
    asm volatile(
        "{\n\t.reg .pred p;\n\t"
        "mbarrier.try_wait.parity.acquire.cta.shared::cta.b64 p, [%1], %2;\n\t"
        "selp.b32 %0, 1, 0, p;\n\t}"
        : "=r"(done) : "r"(mbar), "r"(parity) : "memory");
    if (!done) {
        asm volatile(
            "{\n\t.reg .pred P1;\n\t"
            "WL_%=:\n\t"
            "mbarrier.try_wait.parity.acquire.cta.shared::cta.b64 P1, [%0], %1, 0x989680;\n\t"
            "@P1 bra.uni WD_%=;\n\t"
            "bra.uni WL_%=;\n\t"
            "WD_%=:\n\t}"
            :: "r"(mbar), "r"(parity) : "memory");
    }
}

// =============================================================================
// fp32 -> fp16 conversion of xx + 6 weight matrices (one launch)
// =============================================================================
__global__ void convert_kernel(const float* __restrict__ xx,
                               const float* __restrict__ w0, const float* __restrict__ w1,
                               const float* __restrict__ w2, const float* __restrict__ w3,
                               const float* __restrict__ w4, const float* __restrict__ w5)
{
    const uint32_t i4 = blockIdx.x * blockDim.x + threadIdx.x;   // float4 index
    const float* src; uint32_t base4;
    if      (i4 < 1048576u) { src = xx; base4 = 0u; }
    else if (i4 < 1310720u) { src = w0; base4 = 1048576u; }
    else if (i4 < 2359296u) { src = w1; base4 = 1310720u; }
    else if (i4 < 3407872u) { src = w2; base4 = 2359296u; }
    else if (i4 < 4456448u) { src = w3; base4 = 3407872u; }
    else if (i4 < 4718592u) { src = w4; base4 = 4456448u; }
    else                    { src = w5; base4 = 4718592u; }
    const float4 v = ((const float4*)src)[i4 - base4];
    __half2* dst = (__half2*)(g_w16 + (size_t)i4 * 4);
    dst[0] = __floats2half2_rn(v.x, v.y);
    dst[1] = __floats2half2_rn(v.z, v.w);
}

// =============================================================================
// fp16 GEMM: C = A @ W^T (+bias, +ReLU). BM=128, BN=256, BK=32, 3-stage.
// =============================================================================
template<int RELU, int HOUT>
__launch_bounds__(256, 1)
__global__ void gemm16_kernel(const __half* __restrict__ A, long long asr,
                              const __half* __restrict__ W,
                              const float* __restrict__ b1p, const float* __restrict__ b2p,
                              void* __restrict__ Cv, int M, int N, int K)
{
    extern __shared__ __half smh[];
    const int tid = threadIdx.x, lane = tid & 31, warp = tid >> 5;
    const int wm = warp >> 2, wn = warp & 3;
    const int g = lane >> 2, q = lane & 3;
    const int mb = blockIdx.y * 128, nb = blockIdx.x * 256;

    float acc[4][8][4];
#pragma unroll
    for (int a = 0; a < 4; a++)
#pragma unroll
        for (int b = 0; b < 8; b++)
#pragma unroll
            for (int c = 0; c < 4; c++) acc[a][b][c] = 0.0f;

    const uint32_t smb = (uint32_t)__cvta_generic_to_shared(smh);
    const __half* aptr[2]; uint32_t adst[2];
#pragma unroll
    for (int i = 0; i < 2; i++) {
        const int slot = tid + i * 256;
        const int row = slot >> 2, kc = (slot & 3) * 8;
        int gr = mb + row; if (gr > M - 1) gr = M - 1;
        aptr[i] = A + (size_t)gr * asr + kc;
        adst[i] = smb + (uint32_t)((row * HSTR + kc) * 2);
    }
    const __half* bptr[4]; uint32_t bdst[4];
#pragma unroll
    for (int i = 0; i < 4; i++) {
        const int slot = tid + i * 256;
        const int row = slot >> 2, kc = (slot & 3) * 8;
        bptr[i] = W + (size_t)(nb + row) * K + kc;
        bdst[i] = smb + (uint32_t)((G_AT + row * HSTR + kc) * 2);
    }

    const int KT = K >> 5;
    auto issue = [&](int kt) {
        const uint32_t so = (uint32_t)((kt % 3) * G_STG * 2);
        const int koff = kt * 32;
#pragma unroll
        for (int i = 0; i < 2; i++) cp16(adst[i] + so, aptr[i] + koff);
#pragma unroll
        for (int i = 0; i < 4; i++) cp16(bdst[i] + so, bptr[i] + koff);
        cp_commit();
    };

    issue(0); if (KT > 1) issue(1);

    for (int kt = 0; kt < KT; ++kt) {
        if (kt < KT - 1) asm volatile("cp.async.wait_group 1;");
        else             asm volatile("cp.async.wait_group 0;");
        __syncthreads();
        if (kt + 2 < KT) issue(kt + 2);

        const __half* Ab = smh + (kt % 3) * G_STG;
        const __half* Bb = Ab + G_AT;
#pragma unroll
        for (int kk = 0; kk < 32; kk += 16) {
            uint32_t af[4][4], bfr[8][2];
#pragma unroll
            for (int mt = 0; mt < 4; mt++) {
                const int r = wm * 64 + mt * 16 + g;
                af[mt][0] = ld_u32h(Ab + r * HSTR + kk + 2 * q);
                af[mt][1] = ld_u32h(Ab + (r + 8) * HSTR + kk + 2 * q);
                af[mt][2] = ld_u32h(Ab + r * HSTR + kk + 2 * q + 8);
                af[mt][3] = ld_u32h(Ab + (r + 8) * HSTR + kk + 2 * q + 8);
            }
#pragma unroll
            for (int nt = 0; nt < 8; nt++) {
                const int n = wn * 64 + nt * 8 + g;
                bfr[nt][0] = ld_u32h(Bb + n * HSTR + kk + 2 * q);
                bfr[nt][1] = ld_u32h(Bb + n * HSTR + kk + 2 * q + 8);
            }
#pragma unroll
            for (int mt = 0; mt < 4; mt++)
#pragma unroll
                for (int nt = 0; nt < 8; nt++)
                    mma_fp16(acc[mt][nt], af[mt][0], af[mt][1], af[mt][2], af[mt][3],
                             bfr[nt][0], bfr[nt][1]);
        }
    }

#pragma unroll
    for (int mt = 0; mt < 4; mt++) {
#pragma unroll
        for (int nt = 0; nt < 8; nt++) {
            const int row0 = mb + wm * 64 + mt * 16 + g;
            const int col  = nb + wn * 64 + nt * 8 + 2 * q;
            const float b0v = (b1p ? b1p[col]     : 0.f) + (b2p ? b2p[col]     : 0.f);
            const float b1v = (b1p ? b1p[col + 1] : 0.f) + (b2p ? b2p[col + 1] : 0.f);
            float v0 = acc[mt][nt][0] + b0v, v1 = acc[mt][nt][1] + b1v;
            float v2 = acc[mt][nt][2] + b0v, v3 = acc[mt][nt][3] + b1v;
            if (RELU) {
                v0 = fmaxf(v0, 0.f); v1 = fmaxf(v1, 0.f);
                v2 = fmaxf(v2, 0.f); v3 = fmaxf(v3, 0.f);
            }
            if (HOUT) {
                __half* C = (__half*)Cv;
                if (row0 < M)     *(__half2*)(C + (size_t)row0 * N + col)       = __floats2half2_rn(v0, v1);
                if (row0 + 8 < M) *(__half2*)(C + (size_t)(row0 + 8) * N + col) = __floats2half2_rn(v2, v3);
            } else {
                float* C = (float*)Cv;
                if (row0 < M)     *(float2*)(C + (size_t)row0 * N + col)       = make_float2(v0, v1);
                if (row0 + 8 < M) *(float2*)(C + (size_t)(row0 + 8) * N + col) = make_float2(v2, v3);
            }
        }
    }
}

// =============================================================================
// fused lstm1 (fp16): h = sig(o)*tanh(sig(i)*tanh(g)); f gate skipped.
// =============================================================================
__launch_bounds__(256, 1)
__global__ void lstm1_16_kernel(const __half* __restrict__ A, long long asr,
                                const __half* __restrict__ W,
                                const float* __restrict__ bih, const float* __restrict__ bhh,
                                __half* __restrict__ Hout, int M, int K)
{
    extern __shared__ __half smh[];
    const int tid = threadIdx.x, lane = tid & 31, warp = tid >> 5;
    const int wm = warp >> 2, wn = warp & 3;
    const int g = lane >> 2, q = lane & 3;
    const int mb = blockIdx.y * 128, nb = blockIdx.x * 128;

    const uint32_t smb = (uint32_t)__cvta_generic_to_shared(smh);

    const __half* aptr[2]; uint32_t adst[2];
#pragma unroll
    for (int i = 0; i < 2; i++) {
        const int slot = tid + i * 256;
        const int row = slot >> 2, kc = (slot & 3) * 8;
        int gr = mb + row; if (gr > M - 1) gr = M - 1;
        aptr[i] = A + (size_t)gr * asr + kc;
        adst[i] = smb + (uint32_t)((row * HSTR + kc) * 2);
    }
    uint32_t bdst[2]; int brow[2], bkc[2];
#pragma unroll
    for (int i = 0; i < 2; i++) {
        const int slot = tid + i * 256;
        brow[i] = slot >> 2; bkc[i] = (slot & 3) * 8;
        bdst[i] = smb + (uint32_t)(((128 + brow[i]) * HSTR + bkc[i]) * 2);
    }

    const int KT = K >> 5;
    float keep[4][4][4];
    const int gset[3] = {0, 2, 3};

#pragma unroll 1
    for (int ph = 0; ph < 3; ++ph) {
        const int gate = gset[ph];
        const __half* Wb = W + ((size_t)(gate * HH + nb)) * K;

        float acc[4][4][4];
#pragma unroll
        for (int a = 0; a < 4; a++)
#pragma unroll
            for (int b = 0; b < 4; b++)
#pragma unroll
                for (int c = 0; c < 4; c++) acc[a][b][c] = 0.0f;

        auto issue = [&](int kt) {
            const int koff = kt * 32;
            const uint32_t so = (uint32_t)((kt & 3) * L_ST * 2);
#pragma unroll
            for (int i = 0; i < 2; i++) cp16(adst[i] + so, aptr[i] + koff);
#pragma unroll
            for (int i = 0; i < 2; i++) cp16(bdst[i] + so, Wb + (size_t)brow[i] * K + bkc[i] + koff);
            cp_commit();
        };

        const int pre = KT < 3 ? KT : 3;
        for (int s = 0; s < pre; ++s) issue(s);

        for (int kt = 0; kt < KT; ++kt) {
            if (kt < KT - 2)       asm volatile("cp.async.wait_group 2;");
            else if (kt == KT - 2) asm volatile("cp.async.wait_group 1;");
            else                   asm volatile("cp.async.wait_group 0;");
            __syncthreads();
            if (kt + 3 < KT) issue(kt + 3);

            const __half* Ab = smh + (kt & 3) * L_ST;
            const __half* Bb = Ab + 128 * HSTR;
#pragma unroll
            for (int kk = 0; kk < 32; kk += 16) {
                uint32_t af[4][4], bfr[4][2];
#pragma unroll
                for (int mt = 0; mt < 4; mt++) {
                    const int r = wm * 64 + mt * 16 + g;
                    af[mt][0] = ld_u32h(Ab + r * HSTR + kk + 2 * q);
                    af[mt][1] = ld_u32h(Ab + (r + 8) * HSTR + kk + 2 * q);
                    af[mt][2] = ld_u32h(Ab + r * HSTR + kk + 2 * q + 8);
                    af[mt][3] = ld_u32h(Ab + (r + 8) * HSTR + kk + 2 * q + 8);
                }
#pragma unroll
                for (int nt = 0; nt < 4; nt++) {
                    const int n = wn * 32 + nt * 8 + g;
                    bfr[nt][0] = ld_u32h(Bb + n * HSTR + kk + 2 * q);
                    bfr[nt][1] = ld_u32h(Bb + n * HSTR + kk + 2 * q + 8);
                }
#pragma unroll
                for (int mt = 0; mt < 4; mt++)
#pragma unroll
                    for (int nt = 0; nt < 4; nt++)
                        mma_fp16(acc[mt][nt], af[mt][0], af[mt][1], af[mt][2], af[mt][3],
                                 bfr[nt][0], bfr[nt][1]);
            }
        }
        __syncthreads();

#pragma unroll
        for (int mt = 0; mt < 4; mt++) {
#pragma unroll
            for (int nt = 0; nt < 4; nt++) {
                const int gcol = gate * HH + nb + wn * 32 + nt * 8 + 2 * q;
                const float b0 = bih[gcol] + bhh[gcol];
                const float b1 = bih[gcol + 1] + bhh[gcol + 1];
                if (ph == 0) {
                    keep[mt][nt][0] = sigf(acc[mt][nt][0] + b0);
                    keep[mt][nt][1] = sigf(acc[mt][nt][1] + b1);
                    keep[mt][nt][2] = sigf(acc[mt][nt][2] + b0);
                    keep[mt][nt][3] = sigf(acc[mt][nt][3] + b1);
                } else if (ph == 1) {
                    keep[mt][nt][0] *= tanhf(acc[mt][nt][0] + b0);
                    keep[mt][nt][1] *= tanhf(acc[mt][nt][1] + b1);
                    keep[mt][nt][2] *= tanhf(acc[mt][nt][2] + b0);
                    keep[mt][nt][3] *= tanhf(acc[mt][nt][3] + b1);
                } else {
                    const int row0 = mb + wm * 64 + mt * 16 + g;
                    const int colh = nb + wn * 32 + nt * 8 + 2 * q;
                    const float v0 = sigf(acc[mt][nt][0] + b0) * tanhf(keep[mt][nt][0]);
                    const float v1 = sigf(acc[mt][nt][1] + b1) * tanhf(keep[mt][nt][1]);
                    const float v2 = sigf(acc[mt][nt][2] + b0) * tanhf(keep[mt][nt][2]);
                    const float v3 = sigf(acc[mt][nt][3] + b1) * tanhf(keep[mt][nt][3]);
                    if (row0 < M)     *(__half2*)(Hout + (size_t)row0 * HH + colh)       = __floats2half2_rn(v0, v1);
                    if (row0 + 8 < M) *(__half2*)(Hout + (size_t)(row0 + 8) * HH + colh) = __floats2half2_rn(v2, v3);
                }
            }
        }
    }
}

// ------------------------- per-group barrier (64 CTAs) ------------------------
__device__ __forceinline__ void group_bar(int G)
{
    __threadfence();
    __syncthreads();
    if (threadIdx.x == 0) {
        const unsigned gen = g_sense2[G];
        const unsigned arrived = atomicAdd((unsigned*)&g_cnt2[G], 1u);
        if (arrived == 63u) {
            g_cnt2[G] = 0;
            __threadfence();
            atomicAdd((unsigned*)&g_sense2[G], 1u);
        } else {
            while (g_sense2[G] == gen) { __nanosleep(16); }
        }
        __threadfence();
    }
    __syncthreads();
}

// =============================================================================
// RECURRENT LSTM LAYER — batch-split edition
//
// 2 independent groups x 64 CTAs; group G owns batch rows [G*32, G*32+32).
// Each CTA owns 16 h cols (64 gate cols); Whh slab 128 KB fp16 in SMEM.
// Per step: TMA both 32KB h-chunks up-front; warps 0-3/4-7 bind to chunk0/1
// (one mbar_wait per warp). M=32,N=64 mma with 8-way K-split; fp32 partials
// reduced in SMEM. 64-CTA sense-reversing barrier per step.
// =============================================================================
__launch_bounds__(256, 1)
__global__ void recur16_kernel(const float* __restrict__ xg,   // [BT, 4096] fp32
                               const float* __restrict__ Whh,  // [4096, 1024] fp32
                               __half* __restrict__ hs,        // [BT, 1024]
                               __half* __restrict__ hT,        // [2G][2p][32768/2]
                               int write_all)
{
    extern __shared__ char smc[];
    __half* Ws  = (__half*)(smc + R2_WS_B);    // [64][1032]
    __half* tb  = (__half*)(smc + R2_TB_B);    // 2 x 16384 halves
    float* part = (float*)(smc + R2_TB_B);     // overlay: 8 x [32][66] f32

    const uint32_t smb = (uint32_t)__cvta_generic_to_shared(smc);
    const uint32_t tb_sh = smb + R2_TB_B;
    const uint32_t mb0 = smb + R2_MBAR_B, mb1 = mb0 + 8;

    const int tid = threadIdx.x, lane = tid & 31;
    const int wk = tid >> 5;                 // K-split warp index 0..7
    const int g = lane >> 2, q = lane & 3;
    const int G  = blockIdx.x >> 6;          // group 0/1
    const int cg = blockIdx.x & 63;          // cta within group
    const int n0h = cg * 16;                 // first owned h col
    const int chn = wk >> 2;                 // warp's chunk
    const uint32_t mb_my = chn ? mb1 : mb0;

    if (tid == 0) { mbar_init(mb0, 1); mbar_init(mb1, 1); }

    // Whh slab fp16: packed row c = gate*16 + j  <-  Whh[gate*HH + n0h + j]
#pragma unroll 1
    for (int c = 0; c < 64; c++) {
        const int row = (c >> 4) * HH + n0h + (c & 15);
        const float4 v = *(const float4*)(Whh + (size_t)row * HH + tid * 4);
        __half* d = Ws + c * 1032 + tid * 4;
        d[0] = __float2half_rn(v.x); d[1] = __float2half_rn(v.y);
        d[2] = __float2half_rn(v.z); d[3] = __float2half_rn(v.w);
    }
    __syncthreads();

    __half* hTg = hT + G * 65536;            // this group's [2][32768]
    const __half* tb_c = tb + chn * 16384;

    // elementwise / h-store mapping (32 rows x 16 cols, 2 outputs/thread)
    const int j = tid & 15, r0 = tid >> 4, r1 = r0 + 16;
    const int brow0 = G * 32 + r0, brow1 = G * 32 + r1;
    const int k_own = n0h + j;
    const int seg_own = k_own >> 1;                  // 0..511
    const int c_own = seg_own >> 8;
    const int pos_base = (seg_own & 255) * 64 + (k_own & 1);
    const int xr_own = 16 * (seg_own & 3);
    float cs0 = 0.f, cs1 = 0.f;

    for (int t = 0; t < TT; t++) {
        const __half* hsrc = hTg + (size_t)(t & 1) * 32768;

        if (t > 0 && tid == 0) {
            mbar_expect(mb0, 32768);
            bulk_g2s(tb_sh, hsrc, 32768, mb0);
            mbar_expect(mb1, 32768);
            bulk_g2s(tb_sh + 32768u, hsrc + 16384, 32768, mb1);
        }

        // xg prefetch (overlaps copy + mma)
        const size_t x0 = ((size_t)(brow0 * TT + t)) * G4 + k_own;
        const size_t x1 = ((size_t)(brow1 * TT + t)) * G4 + k_own;
        const float xi0 = xg[x0], xf0 = xg[x0 + 1024], xgg0 = xg[x0 + 2048], xo0 = xg[x0 + 3072];
        const float xi1 = xg[x1], xf1 = xg[x1 + 1024], xgg1 = xg[x1 + 2048], xo1 = xg[x1 + 3072];

        if (t > 0) {
            float acc[2][8][4];
#pragma unroll
            for (int a = 0; a < 2; a++)
#pragma unroll
                for (int b = 0; b < 8; b++)
#pragma unroll
                    for (int cc = 0; cc < 4; cc++) acc[a][b][cc] = 0.0f;

            mbar_wait(mb_my, (t - 1) & 1u);

            // warp wk: k in [wk*128, wk*128+128)
#pragma unroll
            for (int kk = 0; kk < 8; ++kk) {
                const int seg_local = (wk & 3) * 64 + kk * 8 + q;
                const int xr = 16 * (seg_local & 3);
                const __half* p0 = tb_c + seg_local * 64;
                const __half* p1 = p0 + 256;             // k+8 -> seg+4
                uint32_t a[2][4];
#pragma unroll
                for (int mt = 0; mt < 2; mt++) {
                    const int r = mt * 16 + g;
                    a[mt][0] = ld_u32h(p0 + ((2 * r) ^ xr));
                    a[mt][1] = ld_u32h(p0 + ((2 * (r + 8)) ^ xr));
                    a[mt][2] = ld_u32h(p1 + ((2 * r) ^ xr));
                    a[mt][3] = ld_u32h(p1 + ((2 * (r + 8)) ^ xr));
                }
                const int kglob = wk * 128 + kk * 16 + 2 * q;
                uint32_t bfr[8][2];
#pragma unroll
                for (int nt = 0; nt < 8; nt++) {
                    const int n = nt * 8 + g;
                    bfr[nt][0] = ld_u32h(Ws + n * 1032 + kglob);
                    bfr[nt][1] = ld_u32h(Ws + n * 1032 + kglob + 8);
                }
#pragma unroll
                for (int mt = 0; mt < 2; mt++)
#pragma unroll
                    for (int nt = 0; nt < 8; nt++)
                        mma_fp16(acc[mt][nt], a[mt][0], a[mt][1], a[mt][2], a[mt][3],
                                 bfr[nt][0], bfr[nt][1]);
            }

            __syncthreads();   // chunk reads done before partial overlay

            float* pw = part + wk * P2_SZ;
#pragma unroll
            for (int mt = 0; mt < 2; mt++) {
#pragma unroll
                for (int nt = 0; nt < 8; nt++) {
                    const int r = mt * 16 + g;
                    const int cc = nt * 8 + 2 * q;
                    *(float2*)(pw + r * P2_STR + cc)       = make_float2(acc[mt][nt][0], acc[mt][nt][1]);
                    *(float2*)(pw + (r + 8) * P2_STR + cc) = make_float2(acc[mt][nt][2], acc[mt][nt][3]);
                }
            }
            __syncthreads();
        }

        float gi0 = xi0, gf0 = xf0, gg0 = xgg0, go0 = xo0;
        float gi1 = xi1, gf1 = xf1, gg1 = xgg1, go1 = xo1;
        if (t > 0) {
#pragma unroll
            for (int w = 0; w < 8; w++) {
                const float* pw = part + w * P2_SZ;
                gi0 += pw[r0 * P2_STR + j];      gf0 += pw[r0 * P2_STR + 16 + j];
                gg0 += pw[r0 * P2_STR + 32 + j]; go0 += pw[r0 * P2_STR + 48 + j];
                gi1 += pw[r1 * P2_STR + j];      gf1 += pw[r1 * P2_STR + 16 + j];
                gg1 += pw[r1 * P2_STR + 32 + j]; go1 += pw[r1 * P2_STR + 48 + j];
            }
        }
        cs0 = sigf(gf0) * cs0 + sigf(gi0) * tanhf(gg0);
        cs1 = sigf(gf1) * cs1 + sigf(gi1) * tanhf(gg1);
        const float h0v = sigf(go0) * tanhf(cs0);
        const float h1v = sigf(go1) * tanhf(cs1);

        // transposed swizzled store for next step's bulk copies
        __half* hdst = hTg + (size_t)((t + 1) & 1) * 32768 + c_own * 16384;
        hdst[pos_base + ((2 * r0) ^ xr_own)] = __float2half_rn(h0v);
        hdst[pos_base + ((2 * r1) ^ xr_own)] = __float2half_rn(h1v);
        if (write_all || t == TT - 1) {
            hs[((size_t)(brow0 * TT + t)) * HH + k_own] = __float2half_rn(h0v);
            hs[((size_t)(brow1 * TT + t)) * HH + k_own] = __float2half_rn(h1v);
        }

        if (t < TT - 1) group_bar(G);
    }
}

// ------------------------- final MLP layer 3 ---------------------------------
__global__ void mlp3_kernel(const __half* __restrict__ z2, const float* __restrict__ W3,
                            const float* __restrict__ b3, float* __restrict__ out)
{
    __shared__ float red[8];
    const int b = blockIdx.x;
    float s = 0.f;
    for (int k = threadIdx.x; k < 512; k += 256)
        s += __half2float(z2[b * 512 + k]) * W3[k];
#pragma unroll
    for (int o = 16; o; o >>= 1) s += __shfl_down_sync(0xffffffffu, s, o);
    if ((threadIdx.x & 31) == 0) red[threadIdx.x >> 5] = s;
    __syncthreads();
    if (threadIdx.x < 8) {
        s = red[threadIdx.x];
#pragma unroll
        for (int o = 4; o; o >>= 1) s += __shfl_down_sync(0xffu, s, o);
        if (threadIdx.x == 0) out[b] = s + b3[0];
    }
}

// ------------------------- launcher ------------------------------------------
extern "C" void kernel_launch(void* const* d_in, const int* in_sizes, int n_in,
                              void* d_out, int out_size)
{
    const float* xx       = (const float*)d_in[0];
    const float* l1_Wih0  = (const float*)d_in[1];
    const float* l1_bih0  = (const float*)d_in[2];
    const float* l1_bhh0  = (const float*)d_in[3];
    const float* l1_Wih1  = (const float*)d_in[4];
    const float* l1_bih1  = (const float*)d_in[5];
    const float* l1_bhh1  = (const float*)d_in[6];
    const float* l2_Wih0  = (const float*)d_in[7];
    const float* l2_Whh0  = (const float*)d_in[8];
    const float* l2_bih0  = (const float*)d_in[9];
    const float* l2_bhh0  = (const float*)d_in[10];
    const float* l2_Wih1  = (const float*)d_in[11];
    const float* l2_Whh1  = (const float*)d_in[12];
    const float* l2_bih1  = (const float*)d_in[13];
    const float* l2_bhh1  = (const float*)d_in[14];
    const float* mlp_W1   = (const float*)d_in[15];
    const float* mlp_b1   = (const float*)d_in[16];
    const float* mlp_W2   = (const float*)d_in[17];
    const float* mlp_b2   = (const float*)d_in[18];
    const float* mlp_W3   = (const float*)d_in[19];
    const float* mlp_b3   = (const float*)d_in[20];
    float* out = (float*)d_out;

    void* p;
    cudaGetSymbolAddress(&p, g_gates); float*  gates = (float*)p;
    cudaGetSymbolAddress(&p, g_w16);   __half* w16   = (__half*)p;
    cudaGetSymbolAddress(&p, g_h1);    __half* h1    = (__half*)p;
    cudaGetSymbolAddress(&p, g_h2);    __half* h2    = (__half*)p;
    cudaGetSymbolAddress(&p, g_hT);    __half* hT    = (__half*)p;
    cudaGetSymbolAddress(&p, g_z1);    __half* z1    = (__half*)p;
    cudaGetSymbolAddress(&p, g_z2);    __half* z2    = (__half*)p;

    const int lstm1_smem = 4 * L_ST * 2;     // 81920 B
    const int gemm_smem  = 3 * G_STG * 2;    // 92160 B
    const int recur_smem = R2_SMEM_B;        // 199696 B
    cudaFuncSetAttribute((const void*)gemm16_kernel<0,0>, cudaFuncAttributeMaxDynamicSharedMemorySize, gemm_smem);
    cudaFuncSetAttribute((const void*)gemm16_kernel<1,1>, cudaFuncAttributeMaxDynamicSharedMemorySize, gemm_smem);
    cudaFuncSetAttribute((const void*)lstm1_16_kernel,    cudaFuncAttributeMaxDynamicSharedMemorySize, lstm1_smem);
    cudaFuncSetAttribute((const void*)recur16_kernel,     cudaFuncAttributeMaxDynamicSharedMemorySize, recur_smem);

    const dim3 blk(256);

    // [0] fp32 -> fp16 (xx + 6 weight matrices)
    convert_kernel<<<4849664 / 256, blk>>>(xx, l1_Wih0, l1_Wih1, l2_Wih0, l2_Wih1, mlp_W1, mlp_W2);

    // [1][2] lstm1 (fused, f gate skipped)
    lstm1_16_kernel<<<dim3(HH / 128, BT / 128), blk, lstm1_smem>>>(w16 + X16_OFF, 256, w16 + W_L1A,
                                                                   l1_bih0, l1_bhh0, h1, BT, 256);
    lstm1_16_kernel<<<dim3(HH / 128, BT / 128), blk, lstm1_smem>>>(h1, HH, w16 + W_L1B,
                                                                   l1_bih1, l1_bhh1, h2, BT, HH);

    // [3][4] lstm2 layer 0 xg (split) ; [5] recurrence (profiled by ncu -s 5)
    gemm16_kernel<0,0><<<dim3(G4 / 256, 64), blk, gemm_smem>>>(h2, HH, w16 + W_L2A, l2_bih0, l2_bhh0,
                                                               gates, BT / 2, G4, HH);
    gemm16_kernel<0,0><<<dim3(G4 / 256, 64), blk, gemm_smem>>>(h2 + (size_t)(BT / 2) * HH, HH, w16 + W_L2A,
                                                               l2_bih0, l2_bhh0,
                                                               gates + (size_t)(BT / 2) * G4, BT / 2, G4, HH);
    recur16_kernel<<<128, blk, recur_smem>>>(gates, l2_Whh0, h1, hT, 1);

    // [6][7] lstm2 layer 1
    gemm16_kernel<0,0><<<dim3(G4 / 256, BT / 128), blk, gemm_smem>>>(h1, HH, w16 + W_L2B, l2_bih1, l2_bhh1,
                                                                     gates, BT, G4, HH);
    recur16_kernel<<<128, blk, recur_smem>>>(gates, l2_Whh1, h2, hT, 0);

    // [8][9][10] MLP
    gemm16_kernel<1,1><<<dim3(HH / 256, 1), blk, gemm_smem>>>(h2 + (size_t)(TT - 1) * HH, (long long)TT * HH,
                                                              w16 + W_M1, mlp_b1, nullptr, z1, BB, HH, HH);
    gemm16_kernel<1,1><<<dim3((HH / 2) / 256, 1), blk, gemm_smem>>>(z1, HH, w16 + W_M2, mlp_b2, nullptr,
                                                                    z2, BB, HH / 2, HH);
    mlp3_kernel<<<BB, blk>>>(z2, mlp_W3, mlp_b3, out);
}